// round 6
// baseline (speedup 1.0000x reference)
#include <cuda_runtime.h>
#include <cuda_bf16.h>
#include <math.h>
#include <stdint.h>

#define NHH 8
#define ED 256
#define SQL 1024
#define BSZ 4
#define QKV (NHH*3*ED)   /* 6144 */
#define NE  (NHH*ED)     /* 2048 */
#define TOK (BSZ*SQL)    /* 4096 */

// Scratch (device globals; allocation-free per harness rules)
__device__ float g_proj[(size_t)TOK*QKV];          // (b, s, 6144)
__device__ float g_scores[(size_t)BSZ*NHH*SQL*SQL];// (bh, q, k)
__device__ float g_attn[(size_t)TOK*NE];           // (b,h,s,d) flat == (b,s,2048) raw view

#define BM 128
#define BN 128
#define BK 16          /* one m16n8k16 k-chunk per stage */
#define STRIDE 12      /* uint32 words per smem row (8 used + pad): conflict-free, 48B rows (16B-aligned) */

// Raw-view row remap: head-local seq row s lives at proj row (s/8), col (s%8)*256
__device__ __forceinline__ size_t rowadr(int s) {
    return (size_t)(s >> 3) * QKV + (size_t)(s & 7) * ED;
}

__device__ __forceinline__ unsigned smem_u32(const void* p) {
    unsigned a;
    asm("{ .reg .u64 t; cvta.to.shared.u64 t, %1; cvt.u32.u64 %0, t; }" : "=r"(a) : "l"(p));
    return a;
}

// split fp32 pair (a,b adjacent in k) into packed bf16x2 hi and lo words
__device__ __forceinline__ void split2(float a, float b, unsigned &h, unsigned &l) {
    __nv_bfloat16 ah = __float2bfloat16(a), bh = __float2bfloat16(b);
    float ar = a - __bfloat162float(ah);
    float br = b - __bfloat162float(bh);
    __nv_bfloat16 al = __float2bfloat16(ar), bl = __float2bfloat16(br);
    h = (unsigned)__bfloat16_as_ushort(ah) | ((unsigned)__bfloat16_as_ushort(bh) << 16);
    l = (unsigned)__bfloat16_as_ushort(al) | ((unsigned)__bfloat16_as_ushort(bl) << 16);
}

// store 8 consecutive-k floats (2 float4) of one row into hi/lo smem tiles
__device__ __forceinline__ void store_split(unsigned* H, unsigned* L, int row, int half,
                                            float4 v0, float4 v1) {
    unsigned h0,l0,h1,l1,h2,l2,h3,l3;
    split2(v0.x, v0.y, h0, l0);
    split2(v0.z, v0.w, h1, l1);
    split2(v1.x, v1.y, h2, l2);
    split2(v1.z, v1.w, h3, l3);
    *(uint4*)&H[row*STRIDE + half*4] = make_uint4(h0,h1,h2,h3);
    *(uint4*)&L[row*STRIDE + half*4] = make_uint4(l0,l1,l2,l3);
}

#define MMA_BF16(C, A0, A1, A2, A3, B0, B1)                                      \
    asm volatile("mma.sync.aligned.m16n8k16.row.col.f32.bf16.bf16.f32 "          \
        "{%0,%1,%2,%3}, {%4,%5,%6,%7}, {%8,%9}, {%0,%1,%2,%3};"                  \
        : "+f"((C)[0]), "+f"((C)[1]), "+f"((C)[2]), "+f"((C)[3])                  \
        : "r"(A0), "r"(A1), "r"(A2), "r"(A3), "r"(B0), "r"(B1))

__device__ __forceinline__ void ldsm4(unsigned addr, unsigned r[4]) {
    asm volatile("ldmatrix.sync.aligned.m8n8.x4.shared.b16 {%0,%1,%2,%3}, [%4];"
        : "=r"(r[0]), "=r"(r[1]), "=r"(r[2]), "=r"(r[3]) : "r"(addr));
}

// One BK=16 stage via ldmatrix: 8 warps as 4(m) x 2(n); warp tile 32(m) x 64(n).
// 3 MMAs per tile pair: hi*hi + hi*lo + lo*hi (split-bf16 fp32 emulation).
// Tiles are u32 shared addresses of hi/lo A (128x16 bf16) and B (128x16 bf16, n-major).
__device__ __forceinline__ void compute_stage(
    unsigned Ah, unsigned Al, unsigned Bh, unsigned Bl,
    int wm, int wn, int lane, float acc[2][8][4])
{
    // ldmatrix lane->address map (same for A and B):
    // lanes 0-7: rows 0-7 col-words 0..3 | 8-15: rows 8-15 cw 0 | 16-23: rows 0-7 cw 4 | 24-31: rows 8-15 cw 4
    const int lrow = (lane & 7) | (((lane >> 3) & 1) << 3);
    const int lcw  = (lane >> 4) * 4;
    const unsigned aoff = (unsigned)(((wm*32 + lrow) * STRIDE + lcw) * 4);
    const unsigned boff = (unsigned)(((wn*64 + lrow) * STRIDE + lcw) * 4);

    unsigned ah[2][4], al[2][4];
    #pragma unroll
    for (int mt = 0; mt < 2; mt++) {
        ldsm4(Ah + aoff + (unsigned)(mt*16*STRIDE*4), ah[mt]);
        ldsm4(Al + aoff + (unsigned)(mt*16*STRIDE*4), al[mt]);
    }
    #pragma unroll
    for (int ntp = 0; ntp < 4; ntp++) {
        // one x4 covers two adjacent 8-wide n tiles: regs = {b0(even), b0(odd), b1(even), b1(odd)}
        unsigned bh[4], bl[4];
        ldsm4(Bh + boff + (unsigned)(ntp*16*STRIDE*4), bh);
        ldsm4(Bl + boff + (unsigned)(ntp*16*STRIDE*4), bl);
        #pragma unroll
        for (int sub = 0; sub < 2; sub++) {
            const int nt = ntp*2 + sub;
            #pragma unroll
            for (int mt = 0; mt < 2; mt++) {
                MMA_BF16(acc[mt][nt], ah[mt][0], ah[mt][1], ah[mt][2], ah[mt][3], bh[sub], bh[2+sub]);
                MMA_BF16(acc[mt][nt], ah[mt][0], ah[mt][1], ah[mt][2], ah[mt][3], bl[sub], bl[2+sub]);
                MMA_BF16(acc[mt][nt], al[mt][0], al[mt][1], al[mt][2], al[mt][3], bh[sub], bh[2+sub]);
            }
        }
    }
}

#define SMEM_DECL                                                                 \
    __shared__ __align__(16) unsigned sAh[2][BM*STRIDE], sAl[2][BM*STRIDE];       \
    __shared__ __align__(16) unsigned sBh[2][BN*STRIDE], sBl[2][BN*STRIDE]

// ---------------------------------------------------------------------------
// Kernel 1: proj = x @ w_attn^T + b_attn  (NT, M=4096 N=6144 K=256)
// ---------------------------------------------------------------------------
__global__ void __launch_bounds__(256) proj_gemm(const float* __restrict__ A,
                                                 const float* __restrict__ B,
                                                 const float* __restrict__ bias) {
    SMEM_DECL;
    const int m0 = blockIdx.y * BM, n0 = blockIdx.x * BN;
    const int t = threadIdx.x, lane = t & 31, w = t >> 5;
    const int wm = w >> 1, wn = w & 1;
    const int lr = t >> 1, half = t & 1;
    const float* aptr = A + (size_t)(m0 + lr) * ED + half*8;
    const float* bptr = B + (size_t)(n0 + lr) * ED + half*8;
    const int NS = ED / BK;
    float acc[2][8][4] = {};

    float4 a0 = *(const float4*)aptr, a1 = *(const float4*)(aptr + 4);
    float4 b0 = *(const float4*)bptr, b1 = *(const float4*)(bptr + 4);
    store_split(sAh[0], sAl[0], lr, half, a0, a1);
    store_split(sBh[0], sBl[0], lr, half, b0, b1);
    __syncthreads();

    int buf = 0;
    for (int s = 0; s < NS; s++) {
        if (s + 1 < NS) {
            a0 = *(const float4*)(aptr + (s+1)*BK);
            a1 = *(const float4*)(aptr + (s+1)*BK + 4);
            b0 = *(const float4*)(bptr + (s+1)*BK);
            b1 = *(const float4*)(bptr + (s+1)*BK + 4);
        }
        compute_stage(smem_u32(sAh[buf]), smem_u32(sAl[buf]),
                      smem_u32(sBh[buf]), smem_u32(sBl[buf]), wm, wn, lane, acc);
        if (s + 1 < NS) {
            store_split(sAh[buf^1], sAl[buf^1], lr, half, a0, a1);
            store_split(sBh[buf^1], sBl[buf^1], lr, half, b0, b1);
        }
        __syncthreads();
        buf ^= 1;
    }

    const int g = lane >> 2, q = lane & 3;
    #pragma unroll
    for (int mt = 0; mt < 2; mt++) {
        int row = m0 + wm*32 + mt*16 + g;
        #pragma unroll
        for (int nt = 0; nt < 8; nt++) {
            int col = n0 + wn*64 + nt*8 + q*2;
            float bv0 = bias[col], bv1 = bias[col+1];
            float* d0 = g_proj + (size_t)row * QKV + col;
            float* d1 = g_proj + (size_t)(row+8) * QKV + col;
            *(float2*)d0 = make_float2(acc[mt][nt][0] + bv0, acc[mt][nt][1] + bv1);
            *(float2*)d1 = make_float2(acc[mt][nt][2] + bv0, acc[mt][nt][3] + bv1);
        }
    }
}

// ---------------------------------------------------------------------------
// Kernel 2: scores = (Q·K^T)/16 per (b,h); skip tiles fully above diagonal
// ---------------------------------------------------------------------------
__global__ void __launch_bounds__(256) score_gemm() {
    const int q0 = blockIdx.y * BM, k0 = blockIdx.x * BN;
    if (k0 > q0) return;
    const int bh = blockIdx.z;
    const int b = bh >> 3, h = bh & 7;
    const float* base = g_proj + (size_t)b * SQL * QKV + (size_t)h * 128 * QKV;
    SMEM_DECL;
    const int t = threadIdx.x, lane = t & 31, w = t >> 5;
    const int wm = w >> 1, wn = w & 1;
    const int lr = t >> 1, half = t & 1;
    const float* aptr = base + rowadr(q0 + lr) + half*8;        // Q chunk
    const float* bptr = base + rowadr(k0 + lr) + NE + half*8;   // K chunk
    const int NS = ED / BK;
    float acc[2][8][4] = {};

    float4 a0 = *(const float4*)aptr, a1 = *(const float4*)(aptr + 4);
    float4 b0 = *(const float4*)bptr, b1 = *(const float4*)(bptr + 4);
    store_split(sAh[0], sAl[0], lr, half, a0, a1);
    store_split(sBh[0], sBl[0], lr, half, b0, b1);
    __syncthreads();

    int buf = 0;
    for (int s = 0; s < NS; s++) {
        if (s + 1 < NS) {
            a0 = *(const float4*)(aptr + (s+1)*BK);
            a1 = *(const float4*)(aptr + (s+1)*BK + 4);
            b0 = *(const float4*)(bptr + (s+1)*BK);
            b1 = *(const float4*)(bptr + (s+1)*BK + 4);
        }
        compute_stage(smem_u32(sAh[buf]), smem_u32(sAl[buf]),
                      smem_u32(sBh[buf]), smem_u32(sBl[buf]), wm, wn, lane, acc);
        if (s + 1 < NS) {
            store_split(sAh[buf^1], sAl[buf^1], lr, half, a0, a1);
            store_split(sBh[buf^1], sBl[buf^1], lr, half, b0, b1);
        }
        __syncthreads();
        buf ^= 1;
    }

    float* S = g_scores + (size_t)bh * SQL * SQL;
    const int g = lane >> 2, q = lane & 3;
    #pragma unroll
    for (int mt = 0; mt < 2; mt++) {
        int row = q0 + wm*32 + mt*16 + g;
        #pragma unroll
        for (int nt = 0; nt < 8; nt++) {
            int col = k0 + wn*64 + nt*8 + q*2;
            float* d0 = S + (size_t)row * SQL + col;
            float* d1 = S + (size_t)(row+8) * SQL + col;
            *(float2*)d0 = make_float2(acc[mt][nt][0]*0.0625f, acc[mt][nt][1]*0.0625f);
            *(float2*)d1 = make_float2(acc[mt][nt][2]*0.0625f, acc[mt][nt][3]*0.0625f);
        }
    }
}

// ---------------------------------------------------------------------------
// Kernel 3: causal softmax per row (row = bh*1024 + q)
// ---------------------------------------------------------------------------
__global__ void __launch_bounds__(128) softmax_rows() {
    const int row = blockIdx.x;
    const int q = row & (SQL - 1);
    float* r = g_scores + (size_t)row * SQL;
    const int t = threadIdx.x;
    float v[8];
    float mx = -1e30f;
    #pragma unroll
    for (int i = 0; i < 8; i++) {
        int k = t + i * 128;
        v[i] = (k <= q) ? r[k] : -1e30f;
        mx = fmaxf(mx, v[i]);
    }
    __shared__ float redm[4], reds[4];
    #pragma unroll
    for (int o = 16; o > 0; o >>= 1) mx = fmaxf(mx, __shfl_xor_sync(0xffffffffu, mx, o));
    if ((t & 31) == 0) redm[t >> 5] = mx;
    __syncthreads();
    mx = fmaxf(fmaxf(redm[0], redm[1]), fmaxf(redm[2], redm[3]));
    float sum = 0.f;
    #pragma unroll
    for (int i = 0; i < 8; i++) {
        int k = t + i * 128;
        v[i] = (k <= q) ? expf(v[i] - mx) : 0.f;
        sum += v[i];
    }
    #pragma unroll
    for (int o = 16; o > 0; o >>= 1) sum += __shfl_xor_sync(0xffffffffu, sum, o);
    if ((t & 31) == 0) reds[t >> 5] = sum;
    __syncthreads();
    sum = reds[0] + reds[1] + reds[2] + reds[3];
    float inv = 1.f / sum;
    #pragma unroll
    for (int i = 0; i < 8; i++) r[t + i * 128] = v[i] * inv;
}

// ---------------------------------------------------------------------------
// Kernel 4: O = P @ V  (NN, causal K-loop truncation). V transposed at load.
// ---------------------------------------------------------------------------
__global__ void __launch_bounds__(256) pv_gemm() {
    const int bh = blockIdx.z;
    const int b = bh >> 3, h = bh & 7;
    const int q0 = blockIdx.y * BM;
    const int n0 = blockIdx.x * BN;   // d tile
    const float* Sr = g_scores + (size_t)bh * SQL * SQL;
    const float* vbase = g_proj + (size_t)b * SQL * QKV + (size_t)h * 128 * QKV + 2 * NE;
    SMEM_DECL;
    const int t = threadIdx.x, lane = t & 31, w = t >> 5;
    const int wm = w >> 1, wn = w & 1;
    const int lr = t >> 1, half = t & 1;             // P loader: row lr, k-half
    const int kp = t & 7, d4 = t >> 3;               // V loader: kpair 0..7, d-quad 0..31
    const int NS = (q0 + BM) / BK;
    float acc[2][8][4] = {};

    // prologue
    {
        float4 a0 = *(const float4*)(Sr + (size_t)(q0+lr)*SQL + half*8);
        float4 a1 = *(const float4*)(Sr + (size_t)(q0+lr)*SQL + half*8 + 4);
        store_split(sAh[0], sAl[0], lr, half, a0, a1);
        float4 v0 = *(const float4*)(vbase + rowadr(2*kp)     + n0 + d4*4);
        float4 v1 = *(const float4*)(vbase + rowadr(2*kp + 1) + n0 + d4*4);
        #pragma unroll
        for (int j = 0; j < 4; j++) {
            unsigned hh, ll;
            split2(((const float*)&v0)[j], ((const float*)&v1)[j], hh, ll);
            sBh[0][(d4*4 + j)*STRIDE + kp] = hh;
            sBl[0][(d4*4 + j)*STRIDE + kp] = ll;
        }
    }
    __syncthreads();

    int buf = 0;
    for (int s = 0; s < NS; s++) {
        float4 a0, a1, v0, v1;
        if (s + 1 < NS) {
            int kb = (s+1) * BK;
            a0 = *(const float4*)(Sr + (size_t)(q0+lr)*SQL + kb + half*8);
            a1 = *(const float4*)(Sr + (size_t)(q0+lr)*SQL + kb + half*8 + 4);
            v0 = *(const float4*)(vbase + rowadr(kb + 2*kp)     + n0 + d4*4);
            v1 = *(const float4*)(vbase + rowadr(kb + 2*kp + 1) + n0 + d4*4);
        }
        compute_stage(smem_u32(sAh[buf]), smem_u32(sAl[buf]),
                      smem_u32(sBh[buf]), smem_u32(sBl[buf]), wm, wn, lane, acc);
        if (s + 1 < NS) {
            store_split(sAh[buf^1], sAl[buf^1], lr, half, a0, a1);
            #pragma unroll
            for (int j = 0; j < 4; j++) {
                unsigned hh, ll;
                split2(((const float*)&v0)[j], ((const float*)&v1)[j], hh, ll);
                sBh[buf^1][(d4*4 + j)*STRIDE + kp] = hh;
                sBl[buf^1][(d4*4 + j)*STRIDE + kp] = ll;
            }
        }
        __syncthreads();
        buf ^= 1;
    }

    const int g = lane >> 2, q = lane & 3;
    #pragma unroll
    for (int mt = 0; mt < 2; mt++) {
        int row = q0 + wm*32 + mt*16 + g;
        #pragma unroll
        for (int nt = 0; nt < 8; nt++) {
            int col = n0 + wn*64 + nt*8 + q*2;
            float* d0 = g_attn + ((size_t)bh * SQL + row) * ED + col;
            float* d1 = g_attn + ((size_t)bh * SQL + row + 8) * ED + col;
            *(float2*)d0 = make_float2(acc[mt][nt][0], acc[mt][nt][1]);
            *(float2*)d1 = make_float2(acc[mt][nt][2], acc[mt][nt][3]);
        }
    }
}

// ---------------------------------------------------------------------------
// Kernel 5: out = attn_flat @ w_out^T + b_out (NT, M=4096 N=256 K=2048)
// ---------------------------------------------------------------------------
__global__ void __launch_bounds__(256) out_gemm(const float* __restrict__ B,
                                                const float* __restrict__ bias,
                                                float* __restrict__ C) {
    SMEM_DECL;
    const int m0 = blockIdx.y * BM, n0 = blockIdx.x * BN;
    const int t = threadIdx.x, lane = t & 31, w = t >> 5;
    const int wm = w >> 1, wn = w & 1;
    const int lr = t >> 1, half = t & 1;
    const float* aptr = g_attn + (size_t)(m0 + lr) * NE + half*8;
    const float* bptr = B + (size_t)(n0 + lr) * NE + half*8;
    const int NS = NE / BK;
    float acc[2][8][4] = {};

    float4 a0 = *(const float4*)aptr, a1 = *(const float4*)(aptr + 4);
    float4 b0 = *(const float4*)bptr, b1 = *(const float4*)(bptr + 4);
    store_split(sAh[0], sAl[0], lr, half, a0, a1);
    store_split(sBh[0], sBl[0], lr, half, b0, b1);
    __syncthreads();

    int buf = 0;
    for (int s = 0; s < NS; s++) {
        if (s + 1 < NS) {
            a0 = *(const float4*)(aptr + (s+1)*BK);
            a1 = *(const float4*)(aptr + (s+1)*BK + 4);
            b0 = *(const float4*)(bptr + (s+1)*BK);
            b1 = *(const float4*)(bptr + (s+1)*BK + 4);
        }
        compute_stage(smem_u32(sAh[buf]), smem_u32(sAl[buf]),
                      smem_u32(sBh[buf]), smem_u32(sBl[buf]), wm, wn, lane, acc);
        if (s + 1 < NS) {
            store_split(sAh[buf^1], sAl[buf^1], lr, half, a0, a1);
            store_split(sBh[buf^1], sBl[buf^1], lr, half, b0, b1);
        }
        __syncthreads();
        buf ^= 1;
    }

    const int g = lane >> 2, q = lane & 3;
    #pragma unroll
    for (int mt = 0; mt < 2; mt++) {
        int row = m0 + wm*32 + mt*16 + g;
        #pragma unroll
        for (int nt = 0; nt < 8; nt++) {
            int col = n0 + wn*64 + nt*8 + q*2;
            float bv0 = bias[col], bv1 = bias[col+1];
            float* d0 = C + (size_t)row * ED + col;
            float* d1 = C + (size_t)(row+8) * ED + col;
            *(float2*)d0 = make_float2(acc[mt][nt][0] + bv0, acc[mt][nt][1] + bv1);
            *(float2*)d1 = make_float2(acc[mt][nt][2] + bv0, acc[mt][nt][3] + bv1);
        }
    }
}

extern "C" void kernel_launch(void* const* d_in, const int* in_sizes, int n_in,
                              void* d_out, int out_size) {
    const float* x      = (const float*)d_in[0];
    const float* w_attn = (const float*)d_in[1];
    const float* b_attn = (const float*)d_in[2];
    const float* w_out  = (const float*)d_in[3];
    const float* b_out  = (const float*)d_in[4];
    float* out = (float*)d_out;

    proj_gemm<<<dim3(QKV / BN, TOK / BM), 256>>>(x, w_attn, b_attn);
    score_gemm<<<dim3(SQL / BN, SQL / BM, BSZ * NHH), 256>>>();
    softmax_rows<<<BSZ * NHH * SQL, 128>>>();
    pv_gemm<<<dim3(ED / BN, SQL / BM, BSZ * NHH), 256>>>();
    out_gemm<<<dim3(ED / BN, TOK / BM), 256>>>(w_out, b_out, out);
}

// round 7
// speedup vs baseline: 1.0533x; 1.0533x over previous
#include <cuda_runtime.h>
#include <cuda_bf16.h>
#include <math.h>
#include <stdint.h>

#define NHH 8
#define ED 256
#define SQL 1024
#define BSZ 4
#define QKV (NHH*3*ED)   /* 6144 */
#define NE  (NHH*ED)     /* 2048 */
#define TOK (BSZ*SQL)    /* 4096 */
#define NBH (BSZ*NHH)    /* 32 */

// ---------------------------------------------------------------------------
// Device-global scratch (allocation-free). hi/lo split-bf16 storage:
// a packed u32 word = (elem2i, elem2i+1) as bf16 pair along the GEMM k dim.
// ---------------------------------------------------------------------------
__device__ unsigned g_xh [(size_t)TOK*ED/2],  g_xl [(size_t)TOK*ED/2];   // x rows along d
__device__ unsigned g_wah[(size_t)QKV*ED/2],  g_wal[(size_t)QKV*ED/2];   // w_attn rows along d
__device__ unsigned g_woh[(size_t)ED*NE/2],   g_wol[(size_t)ED*NE/2];    // w_out rows along NE
__device__ unsigned g_qh [(size_t)NBH*SQL*ED/2], g_ql [(size_t)NBH*SQL*ED/2]; // Q [bh][s][d/2]
__device__ unsigned g_kh [(size_t)NBH*SQL*ED/2], g_kl [(size_t)NBH*SQL*ED/2]; // K [bh][s][d/2]
__device__ unsigned g_vth[(size_t)NBH*ED*SQL/2], g_vtl[(size_t)NBH*ED*SQL/2]; // V^T [bh][d][s/2]
__device__ unsigned g_ph [(size_t)NBH*SQL*SQL/2], g_pl [(size_t)NBH*SQL*SQL/2];// P [bh][q][k/2]
__device__ unsigned g_ah [(size_t)TOK*NE/2],  g_al [(size_t)TOK*NE/2];   // attn out (raw view) [tok][k/2]
__device__ float    g_scores[(size_t)NBH*SQL*SQL];                       // fp32 scores

#define BM 128
#define BN 128
#define BK 16
#define STRIDE 12      /* u32 words per smem row: 8 used + 4 pad, conflict-free, 16B-aligned rows */

__device__ __forceinline__ unsigned smem_u32(const void* p) {
    unsigned a;
    asm("{ .reg .u64 t; cvta.to.shared.u64 t, %1; cvt.u32.u64 %0, t; }" : "=r"(a) : "l"(p));
    return a;
}

// split fp32 pair (a,b) into packed bf16x2 hi and lo words
__device__ __forceinline__ void split2(float a, float b, unsigned &h, unsigned &l) {
    __nv_bfloat16 ah = __float2bfloat16(a), bh = __float2bfloat16(b);
    float ar = a - __bfloat162float(ah);
    float br = b - __bfloat162float(bh);
    __nv_bfloat16 al = __float2bfloat16(ar), bl = __float2bfloat16(br);
    h = (unsigned)__bfloat16_as_ushort(ah) | ((unsigned)__bfloat16_as_ushort(bh) << 16);
    l = (unsigned)__bfloat16_as_ushort(al) | ((unsigned)__bfloat16_as_ushort(bl) << 16);
}
__device__ __forceinline__ void split1(float a, unsigned short &h, unsigned short &l) {
    __nv_bfloat16 ah = __float2bfloat16(a);
    __nv_bfloat16 al = __float2bfloat16(a - __bfloat162float(ah));
    h = __bfloat16_as_ushort(ah);
    l = __bfloat16_as_ushort(al);
}

#define MMA_BF16(C, A0, A1, A2, A3, B0, B1)                                      \
    asm volatile("mma.sync.aligned.m16n8k16.row.col.f32.bf16.bf16.f32 "          \
        "{%0,%1,%2,%3}, {%4,%5,%6,%7}, {%8,%9}, {%0,%1,%2,%3};"                  \
        : "+f"((C)[0]), "+f"((C)[1]), "+f"((C)[2]), "+f"((C)[3])                  \
        : "r"(A0), "r"(A1), "r"(A2), "r"(A3), "r"(B0), "r"(B1))

__device__ __forceinline__ void ldsm4(unsigned addr, unsigned r[4]) {
    asm volatile("ldmatrix.sync.aligned.m8n8.x4.shared.b16 {%0,%1,%2,%3}, [%4];"
        : "=r"(r[0]), "=r"(r[1]), "=r"(r[2]), "=r"(r[3]) : "r"(addr));
}

// One BK=16 stage via ldmatrix: 8 warps as 4(m) x 2(n); warp tile 32(m) x 64(n).
// 3 MMAs per tile pair: hi*hi + hi*lo + lo*hi (split-bf16 fp32 emulation).
__device__ __forceinline__ void compute_stage(
    unsigned Ah, unsigned Al, unsigned Bh, unsigned Bl,
    int wm, int wn, int lane, float acc[2][8][4])
{
    const int lrow = (lane & 7) | (((lane >> 3) & 1) << 3);
    const int lcw  = (lane >> 4) * 4;
    const unsigned aoff = (unsigned)(((wm*32 + lrow) * STRIDE + lcw) * 4);
    const unsigned boff = (unsigned)(((wn*64 + lrow) * STRIDE + lcw) * 4);

    unsigned ah[2][4], al[2][4];
    #pragma unroll
    for (int mt = 0; mt < 2; mt++) {
        ldsm4(Ah + aoff + (unsigned)(mt*16*STRIDE*4), ah[mt]);
        ldsm4(Al + aoff + (unsigned)(mt*16*STRIDE*4), al[mt]);
    }
    #pragma unroll
    for (int ntp = 0; ntp < 4; ntp++) {
        unsigned bh[4], bl[4];
        ldsm4(Bh + boff + (unsigned)(ntp*16*STRIDE*4), bh);
        ldsm4(Bl + boff + (unsigned)(ntp*16*STRIDE*4), bl);
        #pragma unroll
        for (int sub = 0; sub < 2; sub++) {
            const int nt = ntp*2 + sub;
            #pragma unroll
            for (int mt = 0; mt < 2; mt++) {
                MMA_BF16(acc[mt][nt], ah[mt][0], ah[mt][1], ah[mt][2], ah[mt][3], bh[sub], bh[2+sub]);
                MMA_BF16(acc[mt][nt], ah[mt][0], ah[mt][1], ah[mt][2], ah[mt][3], bl[sub], bl[2+sub]);
                MMA_BF16(acc[mt][nt], al[mt][0], al[mt][1], al[mt][2], al[mt][3], bh[sub], bh[2+sub]);
            }
        }
    }
}

#define SMEM_DECL                                                                 \
    __shared__ __align__(16) unsigned sAh[2][BM*STRIDE], sAl[2][BM*STRIDE];       \
    __shared__ __align__(16) unsigned sBh[2][BN*STRIDE], sBl[2][BN*STRIDE]

// Generic copy-staging GEMM main loop. aH/aL/bH/bL: per-thread gmem pointers
// (already offset by row and half); per stage s the source word offset is s*8.
#define GEMM_LOOP(NS_, aH, aL, bH, bL)                                            \
    {                                                                             \
        uint4 vah = *(const uint4*)(aH), val_ = *(const uint4*)(aL);              \
        uint4 vbh = *(const uint4*)(bH), vbl = *(const uint4*)(bL);               \
        *(uint4*)&sAh[0][lr*STRIDE + half*4] = vah;                               \
        *(uint4*)&sAl[0][lr*STRIDE + half*4] = val_;                              \
        *(uint4*)&sBh[0][lr*STRIDE + half*4] = vbh;                               \
        *(uint4*)&sBl[0][lr*STRIDE + half*4] = vbl;                               \
        __syncthreads();                                                          \
        int buf = 0;                                                              \
        for (int s = 0; s < (NS_); s++) {                                         \
            if (s + 1 < (NS_)) {                                                  \
                vah = *(const uint4*)((aH) + (s+1)*8);                            \
                val_ = *(const uint4*)((aL) + (s+1)*8);                           \
                vbh = *(const uint4*)((bH) + (s+1)*8);                            \
                vbl = *(const uint4*)((bL) + (s+1)*8);                            \
            }                                                                     \
            compute_stage(smem_u32(sAh[buf]), smem_u32(sAl[buf]),                 \
                          smem_u32(sBh[buf]), smem_u32(sBl[buf]), wm, wn, lane, acc); \
            if (s + 1 < (NS_)) {                                                  \
                *(uint4*)&sAh[buf^1][lr*STRIDE + half*4] = vah;                   \
                *(uint4*)&sAl[buf^1][lr*STRIDE + half*4] = val_;                  \
                *(uint4*)&sBh[buf^1][lr*STRIDE + half*4] = vbh;                   \
                *(uint4*)&sBl[buf^1][lr*STRIDE + half*4] = vbl;                   \
            }                                                                     \
            __syncthreads();                                                      \
            buf ^= 1;                                                             \
        }                                                                         \
    }

// ---------------------------------------------------------------------------
// Kernel 0: pre-split fp32 -> hi/lo packed bf16 pairs
// ---------------------------------------------------------------------------
__global__ void __launch_bounds__(256) split_pairs(const float* __restrict__ src,
                                                   unsigned* __restrict__ H,
                                                   unsigned* __restrict__ L, int nwords) {
    int i = blockIdx.x * 256 + threadIdx.x;
    if (i < nwords) {
        float2 v = ((const float2*)src)[i];
        unsigned h, l;
        split2(v.x, v.y, h, l);
        H[i] = h; L[i] = l;
    }
}

// Q/K epilogue writer: raw-view remap baked in. row = global token, col in [0,2048)
__device__ __forceinline__ void write_qk(unsigned* H, unsigned* L, int row, int col,
                                         float v0, float v1) {
    int b = row >> 10, sp = row & 1023;
    int h = sp >> 7, s = ((sp & 127) << 3) + (col >> 8), d = col & 255;
    size_t idx = ((((size_t)(b*8 + h)) * SQL + s) << 7) + (d >> 1);
    unsigned hh, ll;
    split2(v0, v1, hh, ll);
    H[idx] = hh; L[idx] = ll;
}
// V epilogue writer: transposed [bh][d][s], elements (d,cv) and (d+1,cv)
__device__ __forceinline__ void write_v(int row, int cv, float v0, float v1) {
    int b = row >> 10, sp = row & 1023;
    int h = sp >> 7, s = ((sp & 127) << 3) + (cv >> 8), d = cv & 255;
    size_t base = (((size_t)(b*8 + h)) * ED + d) * SQL + s;
    unsigned short h0, l0, h1, l1;
    split1(v0, h0, l0); split1(v1, h1, l1);
    ((unsigned short*)g_vth)[base] = h0;        ((unsigned short*)g_vtl)[base] = l0;
    ((unsigned short*)g_vth)[base + SQL] = h1;  ((unsigned short*)g_vtl)[base + SQL] = l1;
}

// ---------------------------------------------------------------------------
// Kernel 1: proj = x @ w_attn^T + b_attn; epilogue scatters Q,K,V split-bf16
// ---------------------------------------------------------------------------
__global__ void __launch_bounds__(256) proj_gemm(const float* __restrict__ bias) {
    SMEM_DECL;
    const int m0 = blockIdx.y * BM, n0 = blockIdx.x * BN;
    const int t = threadIdx.x, lane = t & 31, w = t >> 5;
    const int wm = w >> 1, wn = w & 1;
    const int lr = t >> 1, half = t & 1;
    const unsigned* aH = g_xh  + (size_t)(m0 + lr) * 128 + half*4;
    const unsigned* aL = g_xl  + (size_t)(m0 + lr) * 128 + half*4;
    const unsigned* bH = g_wah + (size_t)(n0 + lr) * 128 + half*4;
    const unsigned* bL = g_wal + (size_t)(n0 + lr) * 128 + half*4;
    float acc[2][8][4] = {};
    GEMM_LOOP(ED/BK, aH, aL, bH, bL);

    const int g = lane >> 2, qq = lane & 3;
    #pragma unroll
    for (int mt = 0; mt < 2; mt++) {
        int row = m0 + wm*32 + mt*16 + g;
        #pragma unroll
        for (int nt = 0; nt < 8; nt++) {
            int col = n0 + wn*64 + nt*8 + qq*2;
            float bv0 = bias[col], bv1 = bias[col+1];
            float p0 = acc[mt][nt][0] + bv0, p1 = acc[mt][nt][1] + bv1;  // row
            float p2 = acc[mt][nt][2] + bv0, p3 = acc[mt][nt][3] + bv1;  // row+8
            if (col < NE) {                       // Q chunk
                write_qk(g_qh, g_ql, row,   col, p0, p1);
                write_qk(g_qh, g_ql, row+8, col, p2, p3);
            } else if (col < 2*NE) {              // K chunk
                write_qk(g_kh, g_kl, row,   col - NE, p0, p1);
                write_qk(g_kh, g_kl, row+8, col - NE, p2, p3);
            } else {                              // V chunk (transposed store)
                write_v(row,   col - 2*NE, p0, p1);
                write_v(row+8, col - 2*NE, p2, p3);
            }
        }
    }
}

// ---------------------------------------------------------------------------
// Kernel 2: scores = (Q·K^T)/16; skip tiles fully above diagonal
// ---------------------------------------------------------------------------
__global__ void __launch_bounds__(256) score_gemm() {
    const int q0 = blockIdx.y * BM, k0 = blockIdx.x * BN;
    if (k0 > q0) return;
    const int bh = blockIdx.z;
    SMEM_DECL;
    const int t = threadIdx.x, lane = t & 31, w = t >> 5;
    const int wm = w >> 1, wn = w & 1;
    const int lr = t >> 1, half = t & 1;
    const unsigned* aH = g_qh + ((size_t)bh * SQL + q0 + lr) * 128 + half*4;
    const unsigned* aL = g_ql + ((size_t)bh * SQL + q0 + lr) * 128 + half*4;
    const unsigned* bH = g_kh + ((size_t)bh * SQL + k0 + lr) * 128 + half*4;
    const unsigned* bL = g_kl + ((size_t)bh * SQL + k0 + lr) * 128 + half*4;
    float acc[2][8][4] = {};
    GEMM_LOOP(ED/BK, aH, aL, bH, bL);

    float* S = g_scores + (size_t)bh * SQL * SQL;
    const int g = lane >> 2, qq = lane & 3;
    #pragma unroll
    for (int mt = 0; mt < 2; mt++) {
        int row = q0 + wm*32 + mt*16 + g;
        #pragma unroll
        for (int nt = 0; nt < 8; nt++) {
            int col = k0 + wn*64 + nt*8 + qq*2;
            float* d0 = S + (size_t)row * SQL + col;
            float* d1 = S + (size_t)(row+8) * SQL + col;
            *(float2*)d0 = make_float2(acc[mt][nt][0]*0.0625f, acc[mt][nt][1]*0.0625f);
            *(float2*)d1 = make_float2(acc[mt][nt][2]*0.0625f, acc[mt][nt][3]*0.0625f);
        }
    }
}

// ---------------------------------------------------------------------------
// Kernel 3: causal softmax; writes P as split-bf16 packed pairs along k
// ---------------------------------------------------------------------------
__global__ void __launch_bounds__(128) softmax_rows() {
    const int row = blockIdx.x;
    const int q = row & (SQL - 1);
    const float* r = g_scores + (size_t)row * SQL;
    const int t = threadIdx.x;
    const int k0 = t * 8;
    float v[8];
    float4 x0 = *(const float4*)(r + k0);
    float4 x1 = *(const float4*)(r + k0 + 4);
    v[0]=x0.x; v[1]=x0.y; v[2]=x0.z; v[3]=x0.w;
    v[4]=x1.x; v[5]=x1.y; v[6]=x1.z; v[7]=x1.w;
    float mx = -1e30f;
    #pragma unroll
    for (int i = 0; i < 8; i++) {
        v[i] = (k0 + i <= q) ? v[i] : -1e30f;
        mx = fmaxf(mx, v[i]);
    }
    __shared__ float redm[4], reds[4];
    #pragma unroll
    for (int o = 16; o > 0; o >>= 1) mx = fmaxf(mx, __shfl_xor_sync(0xffffffffu, mx, o));
    if ((t & 31) == 0) redm[t >> 5] = mx;
    __syncthreads();
    mx = fmaxf(fmaxf(redm[0], redm[1]), fmaxf(redm[2], redm[3]));
    float sum = 0.f;
    #pragma unroll
    for (int i = 0; i < 8; i++) {
        v[i] = (k0 + i <= q) ? expf(v[i] - mx) : 0.f;
        sum += v[i];
    }
    #pragma unroll
    for (int o = 16; o > 0; o >>= 1) sum += __shfl_xor_sync(0xffffffffu, sum, o);
    if ((t & 31) == 0) reds[t >> 5] = sum;
    __syncthreads();
    sum = reds[0] + reds[1] + reds[2] + reds[3];
    float inv = 1.f / sum;
    unsigned hh[4], ll[4];
    #pragma unroll
    for (int j = 0; j < 4; j++)
        split2(v[2*j] * inv, v[2*j+1] * inv, hh[j], ll[j]);
    *(uint4*)(g_ph + (size_t)row * 512 + t*4) = make_uint4(hh[0], hh[1], hh[2], hh[3]);
    *(uint4*)(g_pl + (size_t)row * 512 + t*4) = make_uint4(ll[0], ll[1], ll[2], ll[3]);
}

// ---------------------------------------------------------------------------
// Kernel 4: O = P @ V^T-stored (causal truncation); epilogue writes split attn
// ---------------------------------------------------------------------------
__global__ void __launch_bounds__(256) pv_gemm() {
    const int bh = blockIdx.z;
    const int q0 = (int)(gridDim.y - 1 - blockIdx.y) * BM;   // heavy tiles first
    const int n0 = blockIdx.x * BN;                          // d tile
    SMEM_DECL;
    const int t = threadIdx.x, lane = t & 31, w = t >> 5;
    const int wm = w >> 1, wn = w & 1;
    const int lr = t >> 1, half = t & 1;
    const int NS = (q0 + BM) / BK;                           // P == 0 beyond diagonal
    const unsigned* aH = g_ph  + ((size_t)bh * SQL + q0 + lr) * 512 + half*4;
    const unsigned* aL = g_pl  + ((size_t)bh * SQL + q0 + lr) * 512 + half*4;
    const unsigned* bH = g_vth + ((size_t)bh * ED + n0 + lr) * 512 + half*4;
    const unsigned* bL = g_vtl + ((size_t)bh * ED + n0 + lr) * 512 + half*4;
    float acc[2][8][4] = {};
    GEMM_LOOP(NS, aH, aL, bH, bL);

    const int g = lane >> 2, qq = lane & 3;
    #pragma unroll
    for (int mt = 0; mt < 2; mt++) {
        int row = q0 + wm*32 + mt*16 + g;
        #pragma unroll
        for (int nt = 0; nt < 8; nt++) {
            int col = n0 + wn*64 + nt*8 + qq*2;
            size_t i0 = ((size_t)bh * SQL + row) * 128 + (col >> 1);
            size_t i1 = ((size_t)bh * SQL + row + 8) * 128 + (col >> 1);
            unsigned hh, ll;
            split2(acc[mt][nt][0], acc[mt][nt][1], hh, ll);
            g_ah[i0] = hh; g_al[i0] = ll;
            split2(acc[mt][nt][2], acc[mt][nt][3], hh, ll);
            g_ah[i1] = hh; g_al[i1] = ll;
        }
    }
}

// ---------------------------------------------------------------------------
// Kernel 5: out = attn_flat @ w_out^T + b_out (fp32 output)
// ---------------------------------------------------------------------------
__global__ void __launch_bounds__(256) out_gemm(const float* __restrict__ bias,
                                                float* __restrict__ C) {
    SMEM_DECL;
    const int m0 = blockIdx.y * BM, n0 = blockIdx.x * BN;
    const int t = threadIdx.x, lane = t & 31, w = t >> 5;
    const int wm = w >> 1, wn = w & 1;
    const int lr = t >> 1, half = t & 1;
    const unsigned* aH = g_ah  + (size_t)(m0 + lr) * 1024 + half*4;
    const unsigned* aL = g_al  + (size_t)(m0 + lr) * 1024 + half*4;
    const unsigned* bH = g_woh + (size_t)(n0 + lr) * 1024 + half*4;
    const unsigned* bL = g_wol + (size_t)(n0 + lr) * 1024 + half*4;
    float acc[2][8][4] = {};
    GEMM_LOOP(NE/BK, aH, aL, bH, bL);

    const int g = lane >> 2, qq = lane & 3;
    #pragma unroll
    for (int mt = 0; mt < 2; mt++) {
        int row = m0 + wm*32 + mt*16 + g;
        #pragma unroll
        for (int nt = 0; nt < 8; nt++) {
            int col = n0 + wn*64 + nt*8 + qq*2;
            float bv0 = bias[col], bv1 = bias[col+1];
            float* d0 = C + (size_t)row * ED + col;
            float* d1 = C + (size_t)(row+8) * ED + col;
            *(float2*)d0 = make_float2(acc[mt][nt][0] + bv0, acc[mt][nt][1] + bv1);
            *(float2*)d1 = make_float2(acc[mt][nt][2] + bv0, acc[mt][nt][3] + bv1);
        }
    }
}

extern "C" void kernel_launch(void* const* d_in, const int* in_sizes, int n_in,
                              void* d_out, int out_size) {
    const float* x      = (const float*)d_in[0];
    const float* w_attn = (const float*)d_in[1];
    const float* b_attn = (const float*)d_in[2];
    const float* w_out  = (const float*)d_in[3];
    const float* b_out  = (const float*)d_in[4];
    float* out = (float*)d_out;

    // resolve device-global symbol addresses for split targets
    unsigned *xh, *xl, *wah, *wal, *woh, *wol;
    cudaGetSymbolAddress((void**)&xh,  g_xh);
    cudaGetSymbolAddress((void**)&xl,  g_xl);
    cudaGetSymbolAddress((void**)&wah, g_wah);
    cudaGetSymbolAddress((void**)&wal, g_wal);
    cudaGetSymbolAddress((void**)&woh, g_woh);
    cudaGetSymbolAddress((void**)&wol, g_wol);

    const int NX = TOK*ED/2, NWA = QKV*ED/2, NWO = ED*NE/2;
    split_pairs<<<(NX  + 255)/256, 256>>>(x,      xh,  xl,  NX);
    split_pairs<<<(NWA + 255)/256, 256>>>(w_attn, wah, wal, NWA);
    split_pairs<<<(NWO + 255)/256, 256>>>(w_out,  woh, wol, NWO);

    proj_gemm<<<dim3(QKV/BN, TOK/BM), 256>>>(b_attn);
    score_gemm<<<dim3(SQL/BN, SQL/BM, NBH), 256>>>();
    softmax_rows<<<NBH*SQL, 128>>>();
    pv_gemm<<<dim3(ED/BN, SQL/BM, NBH), 256>>>();
    out_gemm<<<dim3(ED/BN, TOK/BM), 256>>>(b_out, out);
}

// round 8
// speedup vs baseline: 1.1624x; 1.1035x over previous
#include <cuda_runtime.h>
#include <cuda_bf16.h>
#include <math.h>
#include <stdint.h>

#define NHH 8
#define ED 256
#define SQL 1024
#define BSZ 4
#define QKV (NHH*3*ED)   /* 6144 */
#define NE  (NHH*ED)     /* 2048 */
#define TOK (BSZ*SQL)    /* 4096 */
#define NBH (BSZ*NHH)    /* 32 */

// ---------------------------------------------------------------------------
// Device-global scratch. hi/lo split-bf16: packed u32 = (elem2i, elem2i+1).
// ---------------------------------------------------------------------------
__device__ unsigned g_xh [(size_t)TOK*ED/2],  g_xl [(size_t)TOK*ED/2];
__device__ unsigned g_wah[(size_t)QKV*ED/2],  g_wal[(size_t)QKV*ED/2];
__device__ unsigned g_woh[(size_t)ED*NE/2],   g_wol[(size_t)ED*NE/2];
__device__ unsigned g_qh [(size_t)NBH*SQL*ED/2], g_ql [(size_t)NBH*SQL*ED/2];
__device__ unsigned g_kh [(size_t)NBH*SQL*ED/2], g_kl [(size_t)NBH*SQL*ED/2];
__device__ unsigned g_vth[(size_t)NBH*ED*SQL/2], g_vtl[(size_t)NBH*ED*SQL/2];
__device__ unsigned g_ph [(size_t)NBH*SQL*SQL/2], g_pl [(size_t)NBH*SQL*SQL/2];
__device__ unsigned g_ah [(size_t)TOK*NE/2],  g_al [(size_t)TOK*NE/2];
__device__ float    g_scores[(size_t)NBH*SQL*SQL];

#define BM 128
#define BN 128
#define BK 16
#define STRIDE 12       /* u32 words per smem row: 8 used + 4 pad */
#define STG_B 24576u    /* bytes per pipeline stage (4 tiles x 1536 words) */
#define NPIPE 3
#define SMEM_SZ (NPIPE*24576)

__device__ __forceinline__ unsigned smem_u32(const void* p) {
    unsigned a;
    asm("{ .reg .u64 t; cvta.to.shared.u64 t, %1; cvt.u32.u64 %0, t; }" : "=r"(a) : "l"(p));
    return a;
}

__device__ __forceinline__ void split2(float a, float b, unsigned &h, unsigned &l) {
    __nv_bfloat16 ah = __float2bfloat16(a), bh = __float2bfloat16(b);
    float ar = a - __bfloat162float(ah);
    float br = b - __bfloat162float(bh);
    __nv_bfloat16 al = __float2bfloat16(ar), bl = __float2bfloat16(br);
    h = (unsigned)__bfloat16_as_ushort(ah) | ((unsigned)__bfloat16_as_ushort(bh) << 16);
    l = (unsigned)__bfloat16_as_ushort(al) | ((unsigned)__bfloat16_as_ushort(bl) << 16);
}
__device__ __forceinline__ void split1(float a, unsigned short &h, unsigned short &l) {
    __nv_bfloat16 ah = __float2bfloat16(a);
    __nv_bfloat16 al = __float2bfloat16(a - __bfloat162float(ah));
    h = __bfloat16_as_ushort(ah);
    l = __bfloat16_as_ushort(al);
}

#define MMA_BF16(C, A0, A1, A2, A3, B0, B1)                                      \
    asm volatile("mma.sync.aligned.m16n8k16.row.col.f32.bf16.bf16.f32 "          \
        "{%0,%1,%2,%3}, {%4,%5,%6,%7}, {%8,%9}, {%0,%1,%2,%3};"                  \
        : "+f"((C)[0]), "+f"((C)[1]), "+f"((C)[2]), "+f"((C)[3])                  \
        : "r"(A0), "r"(A1), "r"(A2), "r"(A3), "r"(B0), "r"(B1))

__device__ __forceinline__ void ldsm4(unsigned addr, unsigned r[4]) {
    asm volatile("ldmatrix.sync.aligned.m8n8.x4.shared.b16 {%0,%1,%2,%3}, [%4];"
        : "=r"(r[0]), "=r"(r[1]), "=r"(r[2]), "=r"(r[3]) : "r"(addr));
}

// One BK=16 stage via ldmatrix: 8 warps as 4(m) x 2(n); warp tile 32(m) x 64(n).
// 3 MMAs per tile pair: hi*hi + hi*lo + lo*hi.
__device__ __forceinline__ void compute_stage(
    unsigned Ah, unsigned Al, unsigned Bh, unsigned Bl,
    int wm, int wn, int lane, float acc[2][8][4])
{
    const int lrow = (lane & 7) | (((lane >> 3) & 1) << 3);
    const int lcw  = (lane >> 4) * 4;
    const unsigned aoff = (unsigned)(((wm*32 + lrow) * STRIDE + lcw) * 4);
    const unsigned boff = (unsigned)(((wn*64 + lrow) * STRIDE + lcw) * 4);

    unsigned ah[2][4], al[2][4];
    #pragma unroll
    for (int mt = 0; mt < 2; mt++) {
        ldsm4(Ah + aoff + (unsigned)(mt*16*STRIDE*4), ah[mt]);
        ldsm4(Al + aoff + (unsigned)(mt*16*STRIDE*4), al[mt]);
    }
    #pragma unroll
    for (int ntp = 0; ntp < 4; ntp++) {
        unsigned bh[4], bl[4];
        ldsm4(Bh + boff + (unsigned)(ntp*16*STRIDE*4), bh);
        ldsm4(Bl + boff + (unsigned)(ntp*16*STRIDE*4), bl);
        #pragma unroll
        for (int sub = 0; sub < 2; sub++) {
            const int nt = ntp*2 + sub;
            #pragma unroll
            for (int mt = 0; mt < 2; mt++) {
                MMA_BF16(acc[mt][nt], ah[mt][0], ah[mt][1], ah[mt][2], ah[mt][3], bh[sub], bh[2+sub]);
                MMA_BF16(acc[mt][nt], ah[mt][0], ah[mt][1], ah[mt][2], ah[mt][3], bl[sub], bl[2+sub]);
                MMA_BF16(acc[mt][nt], al[mt][0], al[mt][1], al[mt][2], al[mt][3], bh[sub], bh[2+sub]);
            }
        }
    }
}

#define CPA(dst, src) \
    asm volatile("cp.async.cg.shared.global [%0], [%1], 16;" :: "r"(dst), "l"(src))

// stage s into ring buffer b: 4 x 16B cp.async per thread + one commit
#define ISSUE_STAGE(s, b) {                                                       \
    unsigned d_ = smb + (unsigned)(b)*STG_B + (unsigned)(lr*48 + half*16);        \
    CPA(d_,          aH + (size_t)(s)*8);                                         \
    CPA(d_ + 6144u,  aL + (size_t)(s)*8);                                         \
    CPA(d_ + 12288u, bH + (size_t)(s)*8);                                         \
    CPA(d_ + 18432u, bL + (size_t)(s)*8);                                         \
    asm volatile("cp.async.commit_group;" ::: "memory"); }

// Main loop: 3-stage cp.async pipeline, one barrier per stage.
#define GEMM_LOOP(NS_) {                                                          \
    ISSUE_STAGE(0, 0);                                                            \
    ISSUE_STAGE(1, 1);                                                            \
    for (int i = 0; i < (NS_); i++) {                                             \
        const unsigned bb = smb + (unsigned)(i % 3) * STG_B;                      \
        if (i + 1 < (NS_)) { asm volatile("cp.async.wait_group 1;" ::: "memory"); }\
        else               { asm volatile("cp.async.wait_group 0;" ::: "memory"); }\
        __syncthreads();                                                          \
        compute_stage(bb, bb + 6144u, bb + 12288u, bb + 18432u, wm, wn, lane, acc);\
        if (i + 2 < (NS_)) ISSUE_STAGE(i + 2, (i + 2) % 3);                       \
        __syncthreads();                                                          \
    } }

// ---------------------------------------------------------------------------
// Kernel 0: pre-split fp32 -> hi/lo packed bf16 pairs
// ---------------------------------------------------------------------------
__global__ void __launch_bounds__(256) split_pairs(const float* __restrict__ src,
                                                   unsigned* __restrict__ H,
                                                   unsigned* __restrict__ L, int nwords) {
    int i = blockIdx.x * 256 + threadIdx.x;
    if (i < nwords) {
        float2 v = ((const float2*)src)[i];
        unsigned h, l;
        split2(v.x, v.y, h, l);
        H[i] = h; L[i] = l;
    }
}

// Q/K epilogue writer: raw-view remap baked in
__device__ __forceinline__ void write_qk(unsigned* H, unsigned* L, int row, int col,
                                         float v0, float v1) {
    int b = row >> 10, sp = row & 1023;
    int h = sp >> 7, s = ((sp & 127) << 3) + (col >> 8), d = col & 255;
    size_t idx = ((((size_t)(b*8 + h)) * SQL + s) << 7) + (d >> 1);
    unsigned hh, ll;
    split2(v0, v1, hh, ll);
    H[idx] = hh; L[idx] = ll;
}
// V epilogue writer: transposed [bh][d][s]
__device__ __forceinline__ void write_v(int row, int cv, float v0, float v1) {
    int b = row >> 10, sp = row & 1023;
    int h = sp >> 7, s = ((sp & 127) << 3) + (cv >> 8), d = cv & 255;
    size_t base = (((size_t)(b*8 + h)) * ED + d) * SQL + s;
    unsigned short h0, l0, h1, l1;
    split1(v0, h0, l0); split1(v1, h1, l1);
    ((unsigned short*)g_vth)[base] = h0;        ((unsigned short*)g_vtl)[base] = l0;
    ((unsigned short*)g_vth)[base + SQL] = h1;  ((unsigned short*)g_vtl)[base + SQL] = l1;
}

// ---------------------------------------------------------------------------
// Kernel 1: proj = x @ w_attn^T + b_attn; scatters Q,K,V split-bf16
// ---------------------------------------------------------------------------
__global__ void __launch_bounds__(256, 2) proj_gemm(const float* __restrict__ bias) {
    extern __shared__ unsigned smd[];
    const unsigned smb = smem_u32(smd);
    const int m0 = blockIdx.y * BM, n0 = blockIdx.x * BN;
    const int t = threadIdx.x, lane = t & 31, w = t >> 5;
    const int wm = w >> 1, wn = w & 1;
    const int lr = t >> 1, half = t & 1;
    const unsigned* aH = g_xh  + (size_t)(m0 + lr) * 128 + half*4;
    const unsigned* aL = g_xl  + (size_t)(m0 + lr) * 128 + half*4;
    const unsigned* bH = g_wah + (size_t)(n0 + lr) * 128 + half*4;
    const unsigned* bL = g_wal + (size_t)(n0 + lr) * 128 + half*4;
    float acc[2][8][4] = {};
    GEMM_LOOP(ED/BK);

    const int g = lane >> 2, qq = lane & 3;
    #pragma unroll
    for (int mt = 0; mt < 2; mt++) {
        int row = m0 + wm*32 + mt*16 + g;
        #pragma unroll
        for (int nt = 0; nt < 8; nt++) {
            int col = n0 + wn*64 + nt*8 + qq*2;
            float bv0 = bias[col], bv1 = bias[col+1];
            float p0 = acc[mt][nt][0] + bv0, p1 = acc[mt][nt][1] + bv1;
            float p2 = acc[mt][nt][2] + bv0, p3 = acc[mt][nt][3] + bv1;
            if (col < NE) {
                write_qk(g_qh, g_ql, row,   col, p0, p1);
                write_qk(g_qh, g_ql, row+8, col, p2, p3);
            } else if (col < 2*NE) {
                write_qk(g_kh, g_kl, row,   col - NE, p0, p1);
                write_qk(g_kh, g_kl, row+8, col - NE, p2, p3);
            } else {
                write_v(row,   col - 2*NE, p0, p1);
                write_v(row+8, col - 2*NE, p2, p3);
            }
        }
    }
}

// ---------------------------------------------------------------------------
// Kernel 2: scores = (Q·K^T)/16; skip tiles fully above diagonal
// ---------------------------------------------------------------------------
__global__ void __launch_bounds__(256, 2) score_gemm() {
    const int q0 = blockIdx.y * BM, k0 = blockIdx.x * BN;
    if (k0 > q0) return;
    const int bh = blockIdx.z;
    extern __shared__ unsigned smd[];
    const unsigned smb = smem_u32(smd);
    const int t = threadIdx.x, lane = t & 31, w = t >> 5;
    const int wm = w >> 1, wn = w & 1;
    const int lr = t >> 1, half = t & 1;
    const unsigned* aH = g_qh + ((size_t)bh * SQL + q0 + lr) * 128 + half*4;
    const unsigned* aL = g_ql + ((size_t)bh * SQL + q0 + lr) * 128 + half*4;
    const unsigned* bH = g_kh + ((size_t)bh * SQL + k0 + lr) * 128 + half*4;
    const unsigned* bL = g_kl + ((size_t)bh * SQL + k0 + lr) * 128 + half*4;
    float acc[2][8][4] = {};
    GEMM_LOOP(ED/BK);

    float* S = g_scores + (size_t)bh * SQL * SQL;
    const int g = lane >> 2, qq = lane & 3;
    #pragma unroll
    for (int mt = 0; mt < 2; mt++) {
        int row = q0 + wm*32 + mt*16 + g;
        #pragma unroll
        for (int nt = 0; nt < 8; nt++) {
            int col = k0 + wn*64 + nt*8 + qq*2;
            float* d0 = S + (size_t)row * SQL + col;
            float* d1 = S + (size_t)(row+8) * SQL + col;
            *(float2*)d0 = make_float2(acc[mt][nt][0]*0.0625f, acc[mt][nt][1]*0.0625f);
            *(float2*)d1 = make_float2(acc[mt][nt][2]*0.0625f, acc[mt][nt][3]*0.0625f);
        }
    }
}

// ---------------------------------------------------------------------------
// Kernel 3: causal softmax; writes P split-bf16 packed pairs along k
// ---------------------------------------------------------------------------
__global__ void __launch_bounds__(128) softmax_rows() {
    const int row = blockIdx.x;
    const int q = row & (SQL - 1);
    const float* r = g_scores + (size_t)row * SQL;
    const int t = threadIdx.x;
    const int k0 = t * 8;
    float v[8];
    float4 x0 = *(const float4*)(r + k0);
    float4 x1 = *(const float4*)(r + k0 + 4);
    v[0]=x0.x; v[1]=x0.y; v[2]=x0.z; v[3]=x0.w;
    v[4]=x1.x; v[5]=x1.y; v[6]=x1.z; v[7]=x1.w;
    float mx = -1e30f;
    #pragma unroll
    for (int i = 0; i < 8; i++) {
        v[i] = (k0 + i <= q) ? v[i] : -1e30f;
        mx = fmaxf(mx, v[i]);
    }
    __shared__ float redm[4], reds[4];
    #pragma unroll
    for (int o = 16; o > 0; o >>= 1) mx = fmaxf(mx, __shfl_xor_sync(0xffffffffu, mx, o));
    if ((t & 31) == 0) redm[t >> 5] = mx;
    __syncthreads();
    mx = fmaxf(fmaxf(redm[0], redm[1]), fmaxf(redm[2], redm[3]));
    float sum = 0.f;
    #pragma unroll
    for (int i = 0; i < 8; i++) {
        v[i] = (k0 + i <= q) ? expf(v[i] - mx) : 0.f;
        sum += v[i];
    }
    #pragma unroll
    for (int o = 16; o > 0; o >>= 1) sum += __shfl_xor_sync(0xffffffffu, sum, o);
    if ((t & 31) == 0) reds[t >> 5] = sum;
    __syncthreads();
    sum = reds[0] + reds[1] + reds[2] + reds[3];
    float inv = 1.f / sum;
    unsigned hh[4], ll[4];
    #pragma unroll
    for (int j = 0; j < 4; j++)
        split2(v[2*j] * inv, v[2*j+1] * inv, hh[j], ll[j]);
    *(uint4*)(g_ph + (size_t)row * 512 + t*4) = make_uint4(hh[0], hh[1], hh[2], hh[3]);
    *(uint4*)(g_pl + (size_t)row * 512 + t*4) = make_uint4(ll[0], ll[1], ll[2], ll[3]);
}

// ---------------------------------------------------------------------------
// Kernel 4: O = P @ V (V stored transposed); causal K truncation
// ---------------------------------------------------------------------------
__global__ void __launch_bounds__(256, 2) pv_gemm() {
    const int bh = blockIdx.z;
    const int q0 = (int)(gridDim.y - 1 - blockIdx.y) * BM;   // heavy tiles first
    const int n0 = blockIdx.x * BN;
    extern __shared__ unsigned smd[];
    const unsigned smb = smem_u32(smd);
    const int t = threadIdx.x, lane = t & 31, w = t >> 5;
    const int wm = w >> 1, wn = w & 1;
    const int lr = t >> 1, half = t & 1;
    const int NS = (q0 + BM) / BK;
    const unsigned* aH = g_ph  + ((size_t)bh * SQL + q0 + lr) * 512 + half*4;
    const unsigned* aL = g_pl  + ((size_t)bh * SQL + q0 + lr) * 512 + half*4;
    const unsigned* bH = g_vth + ((size_t)bh * ED + n0 + lr) * 512 + half*4;
    const unsigned* bL = g_vtl + ((size_t)bh * ED + n0 + lr) * 512 + half*4;
    float acc[2][8][4] = {};
    GEMM_LOOP(NS);

    const int g = lane >> 2, qq = lane & 3;
    #pragma unroll
    for (int mt = 0; mt < 2; mt++) {
        int row = q0 + wm*32 + mt*16 + g;
        #pragma unroll
        for (int nt = 0; nt < 8; nt++) {
            int col = n0 + wn*64 + nt*8 + qq*2;
            size_t i0 = ((size_t)bh * SQL + row) * 128 + (col >> 1);
            size_t i1 = ((size_t)bh * SQL + row + 8) * 128 + (col >> 1);
            unsigned hh, ll;
            split2(acc[mt][nt][0], acc[mt][nt][1], hh, ll);
            g_ah[i0] = hh; g_al[i0] = ll;
            split2(acc[mt][nt][2], acc[mt][nt][3], hh, ll);
            g_ah[i1] = hh; g_al[i1] = ll;
        }
    }
}

// ---------------------------------------------------------------------------
// Kernel 5: out = attn_flat @ w_out^T + b_out (fp32 output)
// ---------------------------------------------------------------------------
__global__ void __launch_bounds__(256, 2) out_gemm(const float* __restrict__ bias,
                                                   float* __restrict__ C) {
    extern __shared__ unsigned smd[];
    const unsigned smb = smem_u32(smd);
    const int m0 = blockIdx.y * BM, n0 = blockIdx.x * BN;
    const int t = threadIdx.x, lane = t & 31, w = t >> 5;
    const int wm = w >> 1, wn = w & 1;
    const int lr = t >> 1, half = t & 1;
    const unsigned* aH = g_ah  + (size_t)(m0 + lr) * 1024 + half*4;
    const unsigned* aL = g_al  + (size_t)(m0 + lr) * 1024 + half*4;
    const unsigned* bH = g_woh + (size_t)(n0 + lr) * 1024 + half*4;
    const unsigned* bL = g_wol + (size_t)(n0 + lr) * 1024 + half*4;
    float acc[2][8][4] = {};
    GEMM_LOOP(NE/BK);

    const int g = lane >> 2, qq = lane & 3;
    #pragma unroll
    for (int mt = 0; mt < 2; mt++) {
        int row = m0 + wm*32 + mt*16 + g;
        #pragma unroll
        for (int nt = 0; nt < 8; nt++) {
            int col = n0 + wn*64 + nt*8 + qq*2;
            float bv0 = bias[col], bv1 = bias[col+1];
            float* d0 = C + (size_t)row * ED + col;
            float* d1 = C + (size_t)(row+8) * ED + col;
            *(float2*)d0 = make_float2(acc[mt][nt][0] + bv0, acc[mt][nt][1] + bv1);
            *(float2*)d1 = make_float2(acc[mt][nt][2] + bv0, acc[mt][nt][3] + bv1);
        }
    }
}

extern "C" void kernel_launch(void* const* d_in, const int* in_sizes, int n_in,
                              void* d_out, int out_size) {
    const float* x      = (const float*)d_in[0];
    const float* w_attn = (const float*)d_in[1];
    const float* b_attn = (const float*)d_in[2];
    const float* w_out  = (const float*)d_in[3];
    const float* b_out  = (const float*)d_in[4];
    float* out = (float*)d_out;

    unsigned *xh, *xl, *wah, *wal, *woh, *wol;
    cudaGetSymbolAddress((void**)&xh,  g_xh);
    cudaGetSymbolAddress((void**)&xl,  g_xl);
    cudaGetSymbolAddress((void**)&wah, g_wah);
    cudaGetSymbolAddress((void**)&wal, g_wal);
    cudaGetSymbolAddress((void**)&woh, g_woh);
    cudaGetSymbolAddress((void**)&wol, g_wol);

    cudaFuncSetAttribute(proj_gemm,  cudaFuncAttributeMaxDynamicSharedMemorySize, SMEM_SZ);
    cudaFuncSetAttribute(score_gemm, cudaFuncAttributeMaxDynamicSharedMemorySize, SMEM_SZ);
    cudaFuncSetAttribute(pv_gemm,    cudaFuncAttributeMaxDynamicSharedMemorySize, SMEM_SZ);
    cudaFuncSetAttribute(out_gemm,   cudaFuncAttributeMaxDynamicSharedMemorySize, SMEM_SZ);

    const int NX = TOK*ED/2, NWA = QKV*ED/2, NWO = ED*NE/2;
    split_pairs<<<(NX  + 255)/256, 256>>>(x,      xh,  xl,  NX);
    split_pairs<<<(NWA + 255)/256, 256>>>(w_attn, wah, wal, NWA);
    split_pairs<<<(NWO + 255)/256, 256>>>(w_out,  woh, wol, NWO);

    proj_gemm<<<dim3(QKV/BN, TOK/BM), 256, SMEM_SZ>>>(b_attn);
    score_gemm<<<dim3(SQL/BN, SQL/BM, NBH), 256, SMEM_SZ>>>();
    softmax_rows<<<NBH*SQL, 128>>>();
    pv_gemm<<<dim3(ED/BN, SQL/BM, NBH), 256, SMEM_SZ>>>();
    out_gemm<<<dim3(ED/BN, TOK/BM), 256, SMEM_SZ>>>(b_out, out);
}

// round 9
// speedup vs baseline: 1.1667x; 1.0037x over previous
#include <cuda_runtime.h>
#include <cuda_bf16.h>
#include <math.h>
#include <stdint.h>

#define NHH 8
#define ED 256
#define SQL 1024
#define BSZ 4
#define QKV (NHH*3*ED)   /* 6144 */
#define NE  (NHH*ED)     /* 2048 */
#define TOK (BSZ*SQL)    /* 4096 */
#define NBH (BSZ*NHH)    /* 32 */

// ---------------------------------------------------------------------------
// Device-global scratch. hi/lo split-bf16: packed u32 = (elem2i, elem2i+1).
// ---------------------------------------------------------------------------
__device__ unsigned g_xh [(size_t)TOK*ED/2],  g_xl [(size_t)TOK*ED/2];
__device__ unsigned g_wah[(size_t)QKV*ED/2],  g_wal[(size_t)QKV*ED/2];
__device__ unsigned g_woh[(size_t)ED*NE/2],   g_wol[(size_t)ED*NE/2];
__device__ unsigned g_qh [(size_t)NBH*SQL*ED/2], g_ql [(size_t)NBH*SQL*ED/2];
__device__ unsigned g_kh [(size_t)NBH*SQL*ED/2], g_kl [(size_t)NBH*SQL*ED/2];
__device__ unsigned g_vth[(size_t)NBH*ED*SQL/2], g_vtl[(size_t)NBH*ED*SQL/2];
__device__ unsigned g_ph [(size_t)NBH*SQL*SQL/2], g_pl [(size_t)NBH*SQL*SQL/2];
__device__ unsigned g_ah [(size_t)TOK*NE/2],  g_al [(size_t)TOK*NE/2];
__device__ float    g_scores[(size_t)NBH*SQL*SQL];

#define BM 128
#define BN 128
#define BK 16
#define STRIDE 12       /* u32 words per smem row: 8 used + 4 pad */
#define STG_B 24576u    /* bytes per pipeline stage (4 tiles x 1536 words) */
#define NPIPE 4
#define SMEM_SZ (NPIPE*24576)

__device__ __forceinline__ unsigned smem_u32(const void* p) {
    unsigned a;
    asm("{ .reg .u64 t; cvta.to.shared.u64 t, %1; cvt.u32.u64 %0, t; }" : "=r"(a) : "l"(p));
    return a;
}

__device__ __forceinline__ void split2(float a, float b, unsigned &h, unsigned &l) {
    __nv_bfloat16 ah = __float2bfloat16(a), bh = __float2bfloat16(b);
    float ar = a - __bfloat162float(ah);
    float br = b - __bfloat162float(bh);
    __nv_bfloat16 al = __float2bfloat16(ar), bl = __float2bfloat16(br);
    h = (unsigned)__bfloat16_as_ushort(ah) | ((unsigned)__bfloat16_as_ushort(bh) << 16);
    l = (unsigned)__bfloat16_as_ushort(al) | ((unsigned)__bfloat16_as_ushort(bl) << 16);
}
__device__ __forceinline__ void split1(float a, unsigned short &h, unsigned short &l) {
    __nv_bfloat16 ah = __float2bfloat16(a);
    __nv_bfloat16 al = __float2bfloat16(a - __bfloat162float(ah));
    h = __bfloat16_as_ushort(ah);
    l = __bfloat16_as_ushort(al);
}

#define MMA_BF16(C, A0, A1, A2, A3, B0, B1)                                      \
    asm volatile("mma.sync.aligned.m16n8k16.row.col.f32.bf16.bf16.f32 "          \
        "{%0,%1,%2,%3}, {%4,%5,%6,%7}, {%8,%9}, {%0,%1,%2,%3};"                  \
        : "+f"((C)[0]), "+f"((C)[1]), "+f"((C)[2]), "+f"((C)[3])                  \
        : "r"(A0), "r"(A1), "r"(A2), "r"(A3), "r"(B0), "r"(B1))

__device__ __forceinline__ void ldsm4(unsigned addr, unsigned r[4]) {
    asm volatile("ldmatrix.sync.aligned.m8n8.x4.shared.b16 {%0,%1,%2,%3}, [%4];"
        : "=r"(r[0]), "=r"(r[1]), "=r"(r[2]), "=r"(r[3]) : "r"(addr));
}

// One BK=16 stage via ldmatrix: 8 warps as 4(m) x 2(n); warp tile 32(m) x 64(n).
// 3 MMAs per tile pair: hi*hi + hi*lo + lo*hi.
__device__ __forceinline__ void compute_stage(
    unsigned Ah, unsigned Al, unsigned Bh, unsigned Bl,
    int wm, int wn, int lane, float acc[2][8][4])
{
    const int lrow = (lane & 7) | (((lane >> 3) & 1) << 3);
    const int lcw  = (lane >> 4) * 4;
    const unsigned aoff = (unsigned)(((wm*32 + lrow) * STRIDE + lcw) * 4);
    const unsigned boff = (unsigned)(((wn*64 + lrow) * STRIDE + lcw) * 4);

    unsigned ah[2][4], al[2][4];
    #pragma unroll
    for (int mt = 0; mt < 2; mt++) {
        ldsm4(Ah + aoff + (unsigned)(mt*16*STRIDE*4), ah[mt]);
        ldsm4(Al + aoff + (unsigned)(mt*16*STRIDE*4), al[mt]);
    }
    #pragma unroll
    for (int ntp = 0; ntp < 4; ntp++) {
        unsigned bh[4], bl[4];
        ldsm4(Bh + boff + (unsigned)(ntp*16*STRIDE*4), bh);
        ldsm4(Bl + boff + (unsigned)(ntp*16*STRIDE*4), bl);
        #pragma unroll
        for (int sub = 0; sub < 2; sub++) {
            const int nt = ntp*2 + sub;
            #pragma unroll
            for (int mt = 0; mt < 2; mt++) {
                MMA_BF16(acc[mt][nt], ah[mt][0], ah[mt][1], ah[mt][2], ah[mt][3], bh[sub], bh[2+sub]);
                MMA_BF16(acc[mt][nt], ah[mt][0], ah[mt][1], ah[mt][2], ah[mt][3], bl[sub], bl[2+sub]);
                MMA_BF16(acc[mt][nt], al[mt][0], al[mt][1], al[mt][2], al[mt][3], bh[sub], bh[2+sub]);
            }
        }
    }
}

#define CPA(dst, src) \
    asm volatile("cp.async.cg.shared.global [%0], [%1], 16;" :: "r"(dst), "l"(src))

// stage s into ring buffer b: 4 x 16B cp.async per thread + one commit
#define ISSUE_STAGE(s, b) {                                                       \
    unsigned d_ = smb + (unsigned)(b)*STG_B + (unsigned)(lr*48 + half*16);        \
    CPA(d_,          aH + (size_t)(s)*8);                                         \
    CPA(d_ + 6144u,  aL + (size_t)(s)*8);                                         \
    CPA(d_ + 12288u, bH + (size_t)(s)*8);                                         \
    CPA(d_ + 18432u, bL + (size_t)(s)*8);                                         \
    asm volatile("cp.async.commit_group;" ::: "memory"); }

// Main loop: 4-deep ring, 3 stages in flight, ONE barrier per stage.
// Safety of the missing 2nd barrier: ISSUE(i+3) -> buffer (i+3)&3, touched
// buffers in compute at that moment: stage i only. Buffer (i+3)&3 held stage
// i-1, whose compute finished (in all warps) before this iteration's top
// __syncthreads. No overlap.
#define GEMM_LOOP(NS_) {                                                          \
    ISSUE_STAGE(0, 0);                                                            \
    ISSUE_STAGE(1, 1);                                                            \
    ISSUE_STAGE(2, 2);                                                            \
    for (int i = 0; i < (NS_); i++) {                                             \
        const int rem = (NS_) - 1 - i;                                            \
        if (rem >= 2)      { asm volatile("cp.async.wait_group 2;" ::: "memory"); }\
        else if (rem == 1) { asm volatile("cp.async.wait_group 1;" ::: "memory"); }\
        else               { asm volatile("cp.async.wait_group 0;" ::: "memory"); }\
        __syncthreads();                                                          \
        const unsigned bb = smb + (unsigned)(i & 3) * STG_B;                      \
        compute_stage(bb, bb + 6144u, bb + 12288u, bb + 18432u, wm, wn, lane, acc);\
        if (i + 3 < (NS_)) ISSUE_STAGE(i + 3, (i + 3) & 3);                       \
    } }

// ---------------------------------------------------------------------------
// Kernel 0: pre-split fp32 -> hi/lo packed bf16 pairs
// ---------------------------------------------------------------------------
__global__ void __launch_bounds__(256) split_pairs(const float* __restrict__ src,
                                                   unsigned* __restrict__ H,
                                                   unsigned* __restrict__ L, int nwords) {
    int i = blockIdx.x * 256 + threadIdx.x;
    if (i < nwords) {
        float2 v = ((const float2*)src)[i];
        unsigned h, l;
        split2(v.x, v.y, h, l);
        H[i] = h; L[i] = l;
    }
}

// Q/K epilogue writer: raw-view remap baked in
__device__ __forceinline__ void write_qk(unsigned* H, unsigned* L, int row, int col,
                                         float v0, float v1) {
    int b = row >> 10, sp = row & 1023;
    int h = sp >> 7, s = ((sp & 127) << 3) + (col >> 8), d = col & 255;
    size_t idx = ((((size_t)(b*8 + h)) * SQL + s) << 7) + (d >> 1);
    unsigned hh, ll;
    split2(v0, v1, hh, ll);
    H[idx] = hh; L[idx] = ll;
}
// V epilogue writer: transposed [bh][d][s]
__device__ __forceinline__ void write_v(int row, int cv, float v0, float v1) {
    int b = row >> 10, sp = row & 1023;
    int h = sp >> 7, s = ((sp & 127) << 3) + (cv >> 8), d = cv & 255;
    size_t base = (((size_t)(b*8 + h)) * ED + d) * SQL + s;
    unsigned short h0, l0, h1, l1;
    split1(v0, h0, l0); split1(v1, h1, l1);
    ((unsigned short*)g_vth)[base] = h0;        ((unsigned short*)g_vtl)[base] = l0;
    ((unsigned short*)g_vth)[base + SQL] = h1;  ((unsigned short*)g_vtl)[base + SQL] = l1;
}

// ---------------------------------------------------------------------------
// Kernel 1: proj = x @ w_attn^T + b_attn; scatters Q,K,V split-bf16
// ---------------------------------------------------------------------------
__global__ void __launch_bounds__(256, 2) proj_gemm(const float* __restrict__ bias) {
    extern __shared__ unsigned smd[];
    const unsigned smb = smem_u32(smd);
    const int m0 = blockIdx.y * BM, n0 = blockIdx.x * BN;
    const int t = threadIdx.x, lane = t & 31, w = t >> 5;
    const int wm = w >> 1, wn = w & 1;
    const int lr = t >> 1, half = t & 1;
    const unsigned* aH = g_xh  + (size_t)(m0 + lr) * 128 + half*4;
    const unsigned* aL = g_xl  + (size_t)(m0 + lr) * 128 + half*4;
    const unsigned* bH = g_wah + (size_t)(n0 + lr) * 128 + half*4;
    const unsigned* bL = g_wal + (size_t)(n0 + lr) * 128 + half*4;
    float acc[2][8][4] = {};
    GEMM_LOOP(ED/BK);

    const int g = lane >> 2, qq = lane & 3;
    #pragma unroll
    for (int mt = 0; mt < 2; mt++) {
        int row = m0 + wm*32 + mt*16 + g;
        #pragma unroll
        for (int nt = 0; nt < 8; nt++) {
            int col = n0 + wn*64 + nt*8 + qq*2;
            float bv0 = bias[col], bv1 = bias[col+1];
            float p0 = acc[mt][nt][0] + bv0, p1 = acc[mt][nt][1] + bv1;
            float p2 = acc[mt][nt][2] + bv0, p3 = acc[mt][nt][3] + bv1;
            if (col < NE) {
                write_qk(g_qh, g_ql, row,   col, p0, p1);
                write_qk(g_qh, g_ql, row+8, col, p2, p3);
            } else if (col < 2*NE) {
                write_qk(g_kh, g_kl, row,   col - NE, p0, p1);
                write_qk(g_kh, g_kl, row+8, col - NE, p2, p3);
            } else {
                write_v(row,   col - 2*NE, p0, p1);
                write_v(row+8, col - 2*NE, p2, p3);
            }
        }
    }
}

// ---------------------------------------------------------------------------
// Kernel 2: scores = (Q·K^T)/16; skip tiles fully above diagonal
// ---------------------------------------------------------------------------
__global__ void __launch_bounds__(256, 2) score_gemm() {
    const int q0 = blockIdx.y * BM, k0 = blockIdx.x * BN;
    if (k0 > q0) return;
    const int bh = blockIdx.z;
    extern __shared__ unsigned smd[];
    const unsigned smb = smem_u32(smd);
    const int t = threadIdx.x, lane = t & 31, w = t >> 5;
    const int wm = w >> 1, wn = w & 1;
    const int lr = t >> 1, half = t & 1;
    const unsigned* aH = g_qh + ((size_t)bh * SQL + q0 + lr) * 128 + half*4;
    const unsigned* aL = g_ql + ((size_t)bh * SQL + q0 + lr) * 128 + half*4;
    const unsigned* bH = g_kh + ((size_t)bh * SQL + k0 + lr) * 128 + half*4;
    const unsigned* bL = g_kl + ((size_t)bh * SQL + k0 + lr) * 128 + half*4;
    float acc[2][8][4] = {};
    GEMM_LOOP(ED/BK);

    float* S = g_scores + (size_t)bh * SQL * SQL;
    const int g = lane >> 2, qq = lane & 3;
    #pragma unroll
    for (int mt = 0; mt < 2; mt++) {
        int row = q0 + wm*32 + mt*16 + g;
        #pragma unroll
        for (int nt = 0; nt < 8; nt++) {
            int col = k0 + wn*64 + nt*8 + qq*2;
            float* d0 = S + (size_t)row * SQL + col;
            float* d1 = S + (size_t)(row+8) * SQL + col;
            *(float2*)d0 = make_float2(acc[mt][nt][0]*0.0625f, acc[mt][nt][1]*0.0625f);
            *(float2*)d1 = make_float2(acc[mt][nt][2]*0.0625f, acc[mt][nt][3]*0.0625f);
        }
    }
}

// ---------------------------------------------------------------------------
// Kernel 3: causal softmax; writes P split-bf16 packed pairs along k
// ---------------------------------------------------------------------------
__global__ void __launch_bounds__(128) softmax_rows() {
    const int row = blockIdx.x;
    const int q = row & (SQL - 1);
    const float* r = g_scores + (size_t)row * SQL;
    const int t = threadIdx.x;
    const int k0 = t * 8;
    float v[8];
    float4 x0 = *(const float4*)(r + k0);
    float4 x1 = *(const float4*)(r + k0 + 4);
    v[0]=x0.x; v[1]=x0.y; v[2]=x0.z; v[3]=x0.w;
    v[4]=x1.x; v[5]=x1.y; v[6]=x1.z; v[7]=x1.w;
    float mx = -1e30f;
    #pragma unroll
    for (int i = 0; i < 8; i++) {
        v[i] = (k0 + i <= q) ? v[i] : -1e30f;
        mx = fmaxf(mx, v[i]);
    }
    __shared__ float redm[4], reds[4];
    #pragma unroll
    for (int o = 16; o > 0; o >>= 1) mx = fmaxf(mx, __shfl_xor_sync(0xffffffffu, mx, o));
    if ((t & 31) == 0) redm[t >> 5] = mx;
    __syncthreads();
    mx = fmaxf(fmaxf(redm[0], redm[1]), fmaxf(redm[2], redm[3]));
    float sum = 0.f;
    #pragma unroll
    for (int i = 0; i < 8; i++) {
        v[i] = (k0 + i <= q) ? expf(v[i] - mx) : 0.f;
        sum += v[i];
    }
    #pragma unroll
    for (int o = 16; o > 0; o >>= 1) sum += __shfl_xor_sync(0xffffffffu, sum, o);
    if ((t & 31) == 0) reds[t >> 5] = sum;
    __syncthreads();
    sum = reds[0] + reds[1] + reds[2] + reds[3];
    float inv = 1.f / sum;
    unsigned hh[4], ll[4];
    #pragma unroll
    for (int j = 0; j < 4; j++)
        split2(v[2*j] * inv, v[2*j+1] * inv, hh[j], ll[j]);
    *(uint4*)(g_ph + (size_t)row * 512 + t*4) = make_uint4(hh[0], hh[1], hh[2], hh[3]);
    *(uint4*)(g_pl + (size_t)row * 512 + t*4) = make_uint4(ll[0], ll[1], ll[2], ll[3]);
}

// ---------------------------------------------------------------------------
// Kernel 4: O = P @ V (V stored transposed); causal K truncation
// ---------------------------------------------------------------------------
__global__ void __launch_bounds__(256, 2) pv_gemm() {
    const int bh = blockIdx.z;
    const int q0 = (int)(gridDim.y - 1 - blockIdx.y) * BM;   // heavy tiles first
    const int n0 = blockIdx.x * BN;
    extern __shared__ unsigned smd[];
    const unsigned smb = smem_u32(smd);
    const int t = threadIdx.x, lane = t & 31, w = t >> 5;
    const int wm = w >> 1, wn = w & 1;
    const int lr = t >> 1, half = t & 1;
    const int NS = (q0 + BM) / BK;
    const unsigned* aH = g_ph  + ((size_t)bh * SQL + q0 + lr) * 512 + half*4;
    const unsigned* aL = g_pl  + ((size_t)bh * SQL + q0 + lr) * 512 + half*4;
    const unsigned* bH = g_vth + ((size_t)bh * ED + n0 + lr) * 512 + half*4;
    const unsigned* bL = g_vtl + ((size_t)bh * ED + n0 + lr) * 512 + half*4;
    float acc[2][8][4] = {};
    GEMM_LOOP(NS);

    const int g = lane >> 2, qq = lane & 3;
    #pragma unroll
    for (int mt = 0; mt < 2; mt++) {
        int row = q0 + wm*32 + mt*16 + g;
        #pragma unroll
        for (int nt = 0; nt < 8; nt++) {
            int col = n0 + wn*64 + nt*8 + qq*2;
            size_t i0 = ((size_t)bh * SQL + row) * 128 + (col >> 1);
            size_t i1 = ((size_t)bh * SQL + row + 8) * 128 + (col >> 1);
            unsigned hh, ll;
            split2(acc[mt][nt][0], acc[mt][nt][1], hh, ll);
            g_ah[i0] = hh; g_al[i0] = ll;
            split2(acc[mt][nt][2], acc[mt][nt][3], hh, ll);
            g_ah[i1] = hh; g_al[i1] = ll;
        }
    }
}

// ---------------------------------------------------------------------------
// Kernel 5: out = attn_flat @ w_out^T + b_out (fp32 output)
// ---------------------------------------------------------------------------
__global__ void __launch_bounds__(256, 2) out_gemm(const float* __restrict__ bias,
                                                   float* __restrict__ C) {
    extern __shared__ unsigned smd[];
    const unsigned smb = smem_u32(smd);
    const int m0 = blockIdx.y * BM, n0 = blockIdx.x * BN;
    const int t = threadIdx.x, lane = t & 31, w = t >> 5;
    const int wm = w >> 1, wn = w & 1;
    const int lr = t >> 1, half = t & 1;
    const unsigned* aH = g_ah  + (size_t)(m0 + lr) * 1024 + half*4;
    const unsigned* aL = g_al  + (size_t)(m0 + lr) * 1024 + half*4;
    const unsigned* bH = g_woh + (size_t)(n0 + lr) * 1024 + half*4;
    const unsigned* bL = g_wol + (size_t)(n0 + lr) * 1024 + half*4;
    float acc[2][8][4] = {};
    GEMM_LOOP(NE/BK);

    const int g = lane >> 2, qq = lane & 3;
    #pragma unroll
    for (int mt = 0; mt < 2; mt++) {
        int row = m0 + wm*32 + mt*16 + g;
        #pragma unroll
        for (int nt = 0; nt < 8; nt++) {
            int col = n0 + wn*64 + nt*8 + qq*2;
            float bv0 = bias[col], bv1 = bias[col+1];
            float* d0 = C + (size_t)row * ED + col;
            float* d1 = C + (size_t)(row+8) * ED + col;
            *(float2*)d0 = make_float2(acc[mt][nt][0] + bv0, acc[mt][nt][1] + bv1);
            *(float2*)d1 = make_float2(acc[mt][nt][2] + bv0, acc[mt][nt][3] + bv1);
        }
    }
}

extern "C" void kernel_launch(void* const* d_in, const int* in_sizes, int n_in,
                              void* d_out, int out_size) {
    const float* x      = (const float*)d_in[0];
    const float* w_attn = (const float*)d_in[1];
    const float* b_attn = (const float*)d_in[2];
    const float* w_out  = (const float*)d_in[3];
    const float* b_out  = (const float*)d_in[4];
    float* out = (float*)d_out;

    unsigned *xh, *xl, *wah, *wal, *woh, *wol;
    cudaGetSymbolAddress((void**)&xh,  g_xh);
    cudaGetSymbolAddress((void**)&xl,  g_xl);
    cudaGetSymbolAddress((void**)&wah, g_wah);
    cudaGetSymbolAddress((void**)&wal, g_wal);
    cudaGetSymbolAddress((void**)&woh, g_woh);
    cudaGetSymbolAddress((void**)&wol, g_wol);

    cudaFuncSetAttribute(proj_gemm,  cudaFuncAttributeMaxDynamicSharedMemorySize, SMEM_SZ);
    cudaFuncSetAttribute(score_gemm, cudaFuncAttributeMaxDynamicSharedMemorySize, SMEM_SZ);
    cudaFuncSetAttribute(pv_gemm,    cudaFuncAttributeMaxDynamicSharedMemorySize, SMEM_SZ);
    cudaFuncSetAttribute(out_gemm,   cudaFuncAttributeMaxDynamicSharedMemorySize, SMEM_SZ);

    const int NX = TOK*ED/2, NWA = QKV*ED/2, NWO = ED*NE/2;
    split_pairs<<<(NX  + 255)/256, 256>>>(x,      xh,  xl,  NX);
    split_pairs<<<(NWA + 255)/256, 256>>>(w_attn, wah, wal, NWA);
    split_pairs<<<(NWO + 255)/256, 256>>>(w_out,  woh, wol, NWO);

    proj_gemm<<<dim3(QKV/BN, TOK/BM), 256, SMEM_SZ>>>(b_attn);
    score_gemm<<<dim3(SQL/BN, SQL/BM, NBH), 256, SMEM_SZ>>>();
    softmax_rows<<<NBH*SQL, 128>>>();
    pv_gemm<<<dim3(ED/BN, SQL/BM, NBH), 256, SMEM_SZ>>>();
    out_gemm<<<dim3(ED/BN, TOK/BM), 256, SMEM_SZ>>>(b_out, out);
}

// round 10
// speedup vs baseline: 1.2353x; 1.0588x over previous
#include <cuda_runtime.h>
#include <cuda_bf16.h>
#include <math.h>
#include <stdint.h>

#define NHH 8
#define ED 256
#define SQL 1024
#define BSZ 4
#define QKV (NHH*3*ED)   /* 6144 */
#define NE  (NHH*ED)     /* 2048 */
#define TOK (BSZ*SQL)    /* 4096 */
#define NBH (BSZ*NHH)    /* 32 */

// ---------------------------------------------------------------------------
// Device-global scratch. hi/lo split-bf16: packed u32 = (elem2i, elem2i+1).
// ---------------------------------------------------------------------------
__device__ unsigned g_xh [(size_t)TOK*ED/2],  g_xl [(size_t)TOK*ED/2];
__device__ unsigned g_wah[(size_t)QKV*ED/2],  g_wal[(size_t)QKV*ED/2];
__device__ unsigned g_woh[(size_t)ED*NE/2],   g_wol[(size_t)ED*NE/2];
__device__ unsigned g_qh [(size_t)NBH*SQL*ED/2], g_ql [(size_t)NBH*SQL*ED/2];
__device__ unsigned g_kh [(size_t)NBH*SQL*ED/2], g_kl [(size_t)NBH*SQL*ED/2];
__device__ unsigned g_vth[(size_t)NBH*ED*SQL/2], g_vtl[(size_t)NBH*ED*SQL/2];
__device__ unsigned g_ph [(size_t)NBH*SQL*SQL/2], g_pl [(size_t)NBH*SQL*SQL/2];
__device__ unsigned g_ah [(size_t)TOK*NE/2],  g_al [(size_t)TOK*NE/2];
__device__ float    g_scores[(size_t)NBH*SQL*SQL];

#define BM 128
#define BN 64          /* block tile 128x64; warp tile 32x32 -> 32 acc regs */
#define BK 16
#define STRIDE 12      /* u32 words per smem row: 8 used + 4 pad */
#define STG_B 18432u   /* bytes per stage: A hi/lo 2x6144 + B hi/lo 2x3072 */
#define NPIPE 4
#define SMEM_SZ (NPIPE*18432)   /* 72 KB per CTA -> 3 CTAs/SM */

__device__ __forceinline__ unsigned smem_u32(const void* p) {
    unsigned a;
    asm("{ .reg .u64 t; cvta.to.shared.u64 t, %1; cvt.u32.u64 %0, t; }" : "=r"(a) : "l"(p));
    return a;
}

__device__ __forceinline__ void split2(float a, float b, unsigned &h, unsigned &l) {
    __nv_bfloat16 ah = __float2bfloat16(a), bh = __float2bfloat16(b);
    float ar = a - __bfloat162float(ah);
    float br = b - __bfloat162float(bh);
    __nv_bfloat16 al = __float2bfloat16(ar), bl = __float2bfloat16(br);
    h = (unsigned)__bfloat16_as_ushort(ah) | ((unsigned)__bfloat16_as_ushort(bh) << 16);
    l = (unsigned)__bfloat16_as_ushort(al) | ((unsigned)__bfloat16_as_ushort(bl) << 16);
}
__device__ __forceinline__ void split1(float a, unsigned short &h, unsigned short &l) {
    __nv_bfloat16 ah = __float2bfloat16(a);
    __nv_bfloat16 al = __float2bfloat16(a - __bfloat162float(ah));
    h = __bfloat16_as_ushort(ah);
    l = __bfloat16_as_ushort(al);
}

#define MMA_BF16(C, A0, A1, A2, A3, B0, B1)                                      \
    asm volatile("mma.sync.aligned.m16n8k16.row.col.f32.bf16.bf16.f32 "          \
        "{%0,%1,%2,%3}, {%4,%5,%6,%7}, {%8,%9}, {%0,%1,%2,%3};"                  \
        : "+f"((C)[0]), "+f"((C)[1]), "+f"((C)[2]), "+f"((C)[3])                  \
        : "r"(A0), "r"(A1), "r"(A2), "r"(A3), "r"(B0), "r"(B1))

__device__ __forceinline__ void ldsm4(unsigned addr, unsigned r[4]) {
    asm volatile("ldmatrix.sync.aligned.m8n8.x4.shared.b16 {%0,%1,%2,%3}, [%4];"
        : "=r"(r[0]), "=r"(r[1]), "=r"(r[2]), "=r"(r[3]) : "r"(addr));
}

// One BK=16 stage: 8 warps as 4(m) x 2(n); warp tile 32(m) x 32(n).
// 3 MMAs per tile pair: hi*hi + hi*lo + lo*hi.
__device__ __forceinline__ void compute_stage(
    unsigned Ah, unsigned Al, unsigned Bh, unsigned Bl,
    int wm, int wn, int lane, float acc[2][4][4])
{
    const int lrow = (lane & 7) | (((lane >> 3) & 1) << 3);
    const int lcw  = (lane >> 4) * 4;
    const unsigned aoff = (unsigned)(((wm*32 + lrow) * STRIDE + lcw) * 4);
    const unsigned boff = (unsigned)(((wn*32 + lrow) * STRIDE + lcw) * 4);

    unsigned ah[2][4], al[2][4];
    #pragma unroll
    for (int mt = 0; mt < 2; mt++) {
        ldsm4(Ah + aoff + (unsigned)(mt*16*STRIDE*4), ah[mt]);
        ldsm4(Al + aoff + (unsigned)(mt*16*STRIDE*4), al[mt]);
    }
    #pragma unroll
    for (int ntp = 0; ntp < 2; ntp++) {
        unsigned bh[4], bl[4];
        ldsm4(Bh + boff + (unsigned)(ntp*16*STRIDE*4), bh);
        ldsm4(Bl + boff + (unsigned)(ntp*16*STRIDE*4), bl);
        #pragma unroll
        for (int sub = 0; sub < 2; sub++) {
            const int nt = ntp*2 + sub;
            #pragma unroll
            for (int mt = 0; mt < 2; mt++) {
                MMA_BF16(acc[mt][nt], ah[mt][0], ah[mt][1], ah[mt][2], ah[mt][3], bh[sub], bh[2+sub]);
                MMA_BF16(acc[mt][nt], ah[mt][0], ah[mt][1], ah[mt][2], ah[mt][3], bl[sub], bl[2+sub]);
                MMA_BF16(acc[mt][nt], al[mt][0], al[mt][1], al[mt][2], al[mt][3], bh[sub], bh[2+sub]);
            }
        }
    }
}

#define CPA(dst, src) \
    asm volatile("cp.async.cg.shared.global [%0], [%1], 16;" :: "r"(dst), "l"(src))

// stage s into ring buffer b. A: 256 slots (all threads), B: 128 slots (t<128).
#define ISSUE_STAGE(s, b) {                                                       \
    unsigned d_ = smb + (unsigned)(b)*STG_B + (unsigned)(lr*48 + half*16);        \
    CPA(d_,         aH + (size_t)(s)*8);                                          \
    CPA(d_ + 6144u, aL + (size_t)(s)*8);                                          \
    if (t < 128) {                                                                \
        unsigned e_ = smb + (unsigned)(b)*STG_B + 12288u + (unsigned)(lr*48 + half*16); \
        CPA(e_,         bH + (size_t)(s)*8);                                      \
        CPA(e_ + 3072u, bL + (size_t)(s)*8);                                      \
    }                                                                             \
    asm volatile("cp.async.commit_group;" ::: "memory"); }

// Main loop: 4-deep ring, 3 stages in flight, one barrier per stage.
#define GEMM_LOOP(NS_) {                                                          \
    ISSUE_STAGE(0, 0);                                                            \
    ISSUE_STAGE(1, 1);                                                            \
    ISSUE_STAGE(2, 2);                                                            \
    for (int i = 0; i < (NS_); i++) {                                             \
        const int rem = (NS_) - 1 - i;                                            \
        if (rem >= 2)      { asm volatile("cp.async.wait_group 2;" ::: "memory"); }\
        else if (rem == 1) { asm volatile("cp.async.wait_group 1;" ::: "memory"); }\
        else               { asm volatile("cp.async.wait_group 0;" ::: "memory"); }\
        __syncthreads();                                                          \
        const unsigned bb = smb + (unsigned)(i & 3) * STG_B;                      \
        compute_stage(bb, bb + 6144u, bb + 12288u, bb + 15360u, wm, wn, lane, acc);\
        if (i + 3 < (NS_)) ISSUE_STAGE(i + 3, (i + 3) & 3);                       \
    } }

// ---------------------------------------------------------------------------
// Kernel 0: pre-split fp32 -> hi/lo packed bf16 pairs
// ---------------------------------------------------------------------------
__global__ void __launch_bounds__(256) split_pairs(const float* __restrict__ src,
                                                   unsigned* __restrict__ H,
                                                   unsigned* __restrict__ L, int nwords) {
    int i = blockIdx.x * 256 + threadIdx.x;
    if (i < nwords) {
        float2 v = ((const float2*)src)[i];
        unsigned h, l;
        split2(v.x, v.y, h, l);
        H[i] = h; L[i] = l;
    }
}

// Q/K epilogue writer: raw-view remap baked in
__device__ __forceinline__ void write_qk(unsigned* H, unsigned* L, int row, int col,
                                         float v0, float v1) {
    int b = row >> 10, sp = row & 1023;
    int h = sp >> 7, s = ((sp & 127) << 3) + (col >> 8), d = col & 255;
    size_t idx = ((((size_t)(b*8 + h)) * SQL + s) << 7) + (d >> 1);
    unsigned hh, ll;
    split2(v0, v1, hh, ll);
    H[idx] = hh; L[idx] = ll;
}
// V epilogue writer: transposed [bh][d][s]
__device__ __forceinline__ void write_v(int row, int cv, float v0, float v1) {
    int b = row >> 10, sp = row & 1023;
    int h = sp >> 7, s = ((sp & 127) << 3) + (cv >> 8), d = cv & 255;
    size_t base = (((size_t)(b*8 + h)) * ED + d) * SQL + s;
    unsigned short h0, l0, h1, l1;
    split1(v0, h0, l0); split1(v1, h1, l1);
    ((unsigned short*)g_vth)[base] = h0;        ((unsigned short*)g_vtl)[base] = l0;
    ((unsigned short*)g_vth)[base + SQL] = h1;  ((unsigned short*)g_vtl)[base + SQL] = l1;
}

// ---------------------------------------------------------------------------
// Kernel 1: proj = x @ w_attn^T + b_attn; scatters Q,K,V split-bf16
// ---------------------------------------------------------------------------
__global__ void __launch_bounds__(256, 3) proj_gemm(const float* __restrict__ bias) {
    extern __shared__ unsigned smd[];
    const unsigned smb = smem_u32(smd);
    const int m0 = blockIdx.y * BM, n0 = blockIdx.x * BN;
    const int t = threadIdx.x, lane = t & 31, w = t >> 5;
    const int wm = w >> 1, wn = w & 1;
    const int lr = t >> 1, half = t & 1;
    const unsigned* aH = g_xh  + (size_t)(m0 + lr) * 128 + half*4;
    const unsigned* aL = g_xl  + (size_t)(m0 + lr) * 128 + half*4;
    const unsigned* bH = g_wah + (size_t)(n0 + lr) * 128 + half*4;
    const unsigned* bL = g_wal + (size_t)(n0 + lr) * 128 + half*4;
    float acc[2][4][4] = {};
    GEMM_LOOP(ED/BK);

    const int g = lane >> 2, qq = lane & 3;
    #pragma unroll
    for (int mt = 0; mt < 2; mt++) {
        int row = m0 + wm*32 + mt*16 + g;
        #pragma unroll
        for (int nt = 0; nt < 4; nt++) {
            int col = n0 + wn*32 + nt*8 + qq*2;
            float bv0 = bias[col], bv1 = bias[col+1];
            float p0 = acc[mt][nt][0] + bv0, p1 = acc[mt][nt][1] + bv1;
            float p2 = acc[mt][nt][2] + bv0, p3 = acc[mt][nt][3] + bv1;
            if (col < NE) {
                write_qk(g_qh, g_ql, row,   col, p0, p1);
                write_qk(g_qh, g_ql, row+8, col, p2, p3);
            } else if (col < 2*NE) {
                write_qk(g_kh, g_kl, row,   col - NE, p0, p1);
                write_qk(g_kh, g_kl, row+8, col - NE, p2, p3);
            } else {
                write_v(row,   col - 2*NE, p0, p1);
                write_v(row+8, col - 2*NE, p2, p3);
            }
        }
    }
}

// ---------------------------------------------------------------------------
// Kernel 2: scores = (Q·K^T)/16; skip tiles fully above diagonal
// ---------------------------------------------------------------------------
__global__ void __launch_bounds__(256, 3) score_gemm() {
    const int q0 = blockIdx.y * BM, k0 = blockIdx.x * BN;
    if (k0 > q0 + (BM - 1)) return;
    const int bh = blockIdx.z;
    extern __shared__ unsigned smd[];
    const unsigned smb = smem_u32(smd);
    const int t = threadIdx.x, lane = t & 31, w = t >> 5;
    const int wm = w >> 1, wn = w & 1;
    const int lr = t >> 1, half = t & 1;
    const unsigned* aH = g_qh + ((size_t)bh * SQL + q0 + lr) * 128 + half*4;
    const unsigned* aL = g_ql + ((size_t)bh * SQL + q0 + lr) * 128 + half*4;
    const unsigned* bH = g_kh + ((size_t)bh * SQL + k0 + lr) * 128 + half*4;
    const unsigned* bL = g_kl + ((size_t)bh * SQL + k0 + lr) * 128 + half*4;
    float acc[2][4][4] = {};
    GEMM_LOOP(ED/BK);

    float* S = g_scores + (size_t)bh * SQL * SQL;
    const int g = lane >> 2, qq = lane & 3;
    #pragma unroll
    for (int mt = 0; mt < 2; mt++) {
        int row = q0 + wm*32 + mt*16 + g;
        #pragma unroll
        for (int nt = 0; nt < 4; nt++) {
            int col = k0 + wn*32 + nt*8 + qq*2;
            float* d0 = S + (size_t)row * SQL + col;
            float* d1 = S + (size_t)(row+8) * SQL + col;
            *(float2*)d0 = make_float2(acc[mt][nt][0]*0.0625f, acc[mt][nt][1]*0.0625f);
            *(float2*)d1 = make_float2(acc[mt][nt][2]*0.0625f, acc[mt][nt][3]*0.0625f);
        }
    }
}

// ---------------------------------------------------------------------------
// Kernel 3: causal softmax; writes P split-bf16 packed pairs along k
// ---------------------------------------------------------------------------
__global__ void __launch_bounds__(128) softmax_rows() {
    const int row = blockIdx.x;
    const int q = row & (SQL - 1);
    const float* r = g_scores + (size_t)row * SQL;
    const int t = threadIdx.x;
    const int k0 = t * 8;
    float v[8];
    float4 x0 = *(const float4*)(r + k0);
    float4 x1 = *(const float4*)(r + k0 + 4);
    v[0]=x0.x; v[1]=x0.y; v[2]=x0.z; v[3]=x0.w;
    v[4]=x1.x; v[5]=x1.y; v[6]=x1.z; v[7]=x1.w;
    float mx = -1e30f;
    #pragma unroll
    for (int i = 0; i < 8; i++) {
        v[i] = (k0 + i <= q) ? v[i] : -1e30f;
        mx = fmaxf(mx, v[i]);
    }
    __shared__ float redm[4], reds[4];
    #pragma unroll
    for (int o = 16; o > 0; o >>= 1) mx = fmaxf(mx, __shfl_xor_sync(0xffffffffu, mx, o));
    if ((t & 31) == 0) redm[t >> 5] = mx;
    __syncthreads();
    mx = fmaxf(fmaxf(redm[0], redm[1]), fmaxf(redm[2], redm[3]));
    float sum = 0.f;
    #pragma unroll
    for (int i = 0; i < 8; i++) {
        v[i] = (k0 + i <= q) ? expf(v[i] - mx) : 0.f;
        sum += v[i];
    }
    #pragma unroll
    for (int o = 16; o > 0; o >>= 1) sum += __shfl_xor_sync(0xffffffffu, sum, o);
    if ((t & 31) == 0) reds[t >> 5] = sum;
    __syncthreads();
    sum = reds[0] + reds[1] + reds[2] + reds[3];
    float inv = 1.f / sum;
    unsigned hh[4], ll[4];
    #pragma unroll
    for (int j = 0; j < 4; j++)
        split2(v[2*j] * inv, v[2*j+1] * inv, hh[j], ll[j]);
    *(uint4*)(g_ph + (size_t)row * 512 + t*4) = make_uint4(hh[0], hh[1], hh[2], hh[3]);
    *(uint4*)(g_pl + (size_t)row * 512 + t*4) = make_uint4(ll[0], ll[1], ll[2], ll[3]);
}

// ---------------------------------------------------------------------------
// Kernel 4: O = P @ V (V stored transposed); causal K truncation
// ---------------------------------------------------------------------------
__global__ void __launch_bounds__(256, 3) pv_gemm() {
    const int bh = blockIdx.z;
    const int q0 = (int)(gridDim.y - 1 - blockIdx.y) * BM;   // heavy tiles first
    const int n0 = blockIdx.x * BN;
    extern __shared__ unsigned smd[];
    const unsigned smb = smem_u32(smd);
    const int t = threadIdx.x, lane = t & 31, w = t >> 5;
    const int wm = w >> 1, wn = w & 1;
    const int lr = t >> 1, half = t & 1;
    const int NS = (q0 + BM) / BK;
    const unsigned* aH = g_ph  + ((size_t)bh * SQL + q0 + lr) * 512 + half*4;
    const unsigned* aL = g_pl  + ((size_t)bh * SQL + q0 + lr) * 512 + half*4;
    const unsigned* bH = g_vth + ((size_t)bh * ED + n0 + lr) * 512 + half*4;
    const unsigned* bL = g_vtl + ((size_t)bh * ED + n0 + lr) * 512 + half*4;
    float acc[2][4][4] = {};
    GEMM_LOOP(NS);

    const int g = lane >> 2, qq = lane & 3;
    #pragma unroll
    for (int mt = 0; mt < 2; mt++) {
        int row = q0 + wm*32 + mt*16 + g;
        #pragma unroll
        for (int nt = 0; nt < 4; nt++) {
            int col = n0 + wn*32 + nt*8 + qq*2;
            size_t i0 = ((size_t)bh * SQL + row) * 128 + (col >> 1);
            size_t i1 = ((size_t)bh * SQL + row + 8) * 128 + (col >> 1);
            unsigned hh, ll;
            split2(acc[mt][nt][0], acc[mt][nt][1], hh, ll);
            g_ah[i0] = hh; g_al[i0] = ll;
            split2(acc[mt][nt][2], acc[mt][nt][3], hh, ll);
            g_ah[i1] = hh; g_al[i1] = ll;
        }
    }
}

// ---------------------------------------------------------------------------
// Kernel 5: out = attn_flat @ w_out^T + b_out (fp32 output)
// ---------------------------------------------------------------------------
__global__ void __launch_bounds__(256, 3) out_gemm(const float* __restrict__ bias,
                                                   float* __restrict__ C) {
    extern __shared__ unsigned smd[];
    const unsigned smb = smem_u32(smd);
    const int m0 = blockIdx.y * BM, n0 = blockIdx.x * BN;
    const int t = threadIdx.x, lane = t & 31, w = t >> 5;
    const int wm = w >> 1, wn = w & 1;
    const int lr = t >> 1, half = t & 1;
    const unsigned* aH = g_ah  + (size_t)(m0 + lr) * 1024 + half*4;
    const unsigned* aL = g_al  + (size_t)(m0 + lr) * 1024 + half*4;
    const unsigned* bH = g_woh + (size_t)(n0 + lr) * 1024 + half*4;
    const unsigned* bL = g_wol + (size_t)(n0 + lr) * 1024 + half*4;
    float acc[2][4][4] = {};
    GEMM_LOOP(NE/BK);

    const int g = lane >> 2, qq = lane & 3;
    #pragma unroll
    for (int mt = 0; mt < 2; mt++) {
        int row = m0 + wm*32 + mt*16 + g;
        #pragma unroll
        for (int nt = 0; nt < 4; nt++) {
            int col = n0 + wn*32 + nt*8 + qq*2;
            float bv0 = bias[col], bv1 = bias[col+1];
            float* d0 = C + (size_t)row * ED + col;
            float* d1 = C + (size_t)(row+8) * ED + col;
            *(float2*)d0 = make_float2(acc[mt][nt][0] + bv0, acc[mt][nt][1] + bv1);
            *(float2*)d1 = make_float2(acc[mt][nt][2] + bv0, acc[mt][nt][3] + bv1);
        }
    }
}

extern "C" void kernel_launch(void* const* d_in, const int* in_sizes, int n_in,
                              void* d_out, int out_size) {
    const float* x      = (const float*)d_in[0];
    const float* w_attn = (const float*)d_in[1];
    const float* b_attn = (const float*)d_in[2];
    const float* w_out  = (const float*)d_in[3];
    const float* b_out  = (const float*)d_in[4];
    float* out = (float*)d_out;

    unsigned *xh, *xl, *wah, *wal, *woh, *wol;
    cudaGetSymbolAddress((void**)&xh,  g_xh);
    cudaGetSymbolAddress((void**)&xl,  g_xl);
    cudaGetSymbolAddress((void**)&wah, g_wah);
    cudaGetSymbolAddress((void**)&wal, g_wal);
    cudaGetSymbolAddress((void**)&woh, g_woh);
    cudaGetSymbolAddress((void**)&wol, g_wol);

    cudaFuncSetAttribute(proj_gemm,  cudaFuncAttributeMaxDynamicSharedMemorySize, SMEM_SZ);
    cudaFuncSetAttribute(score_gemm, cudaFuncAttributeMaxDynamicSharedMemorySize, SMEM_SZ);
    cudaFuncSetAttribute(pv_gemm,    cudaFuncAttributeMaxDynamicSharedMemorySize, SMEM_SZ);
    cudaFuncSetAttribute(out_gemm,   cudaFuncAttributeMaxDynamicSharedMemorySize, SMEM_SZ);

    const int NX = TOK*ED/2, NWA = QKV*ED/2, NWO = ED*NE/2;
    split_pairs<<<(NX  + 255)/256, 256>>>(x,      xh,  xl,  NX);
    split_pairs<<<(NWA + 255)/256, 256>>>(w_attn, wah, wal, NWA);
    split_pairs<<<(NWO + 255)/256, 256>>>(w_out,  woh, wol, NWO);

    proj_gemm<<<dim3(QKV/BN, TOK/BM), 256, SMEM_SZ>>>(b_attn);
    score_gemm<<<dim3(SQL/BN, SQL/BM, NBH), 256, SMEM_SZ>>>();
    softmax_rows<<<NBH*SQL, 128>>>();
    pv_gemm<<<dim3(ED/BN, SQL/BM, NBH), 256, SMEM_SZ>>>();
    out_gemm<<<dim3(ED/BN, TOK/BM), 256, SMEM_SZ>>>(b_out, out);
}

// round 11
// speedup vs baseline: 1.3394x; 1.0843x over previous
#include <cuda_runtime.h>
#include <cuda_bf16.h>
#include <math.h>
#include <stdint.h>

#define NHH 8
#define ED 256
#define SQL 1024
#define BSZ 4
#define QKV (NHH*3*ED)   /* 6144 */
#define NE  (NHH*ED)     /* 2048 */
#define TOK (BSZ*SQL)    /* 4096 */
#define NBH (BSZ*NHH)    /* 32 */

// ---------------------------------------------------------------------------
// Device-global scratch. hi/lo split-bf16: packed u32 = (elem2i, elem2i+1).
// Q, K, V all stored natural [bh][s][d/2] (raw-view remap applied at write).
// ---------------------------------------------------------------------------
__device__ unsigned g_xh [(size_t)TOK*ED/2],  g_xl [(size_t)TOK*ED/2];
__device__ unsigned g_wah[(size_t)QKV*ED/2],  g_wal[(size_t)QKV*ED/2];
__device__ unsigned g_woh[(size_t)ED*NE/2],   g_wol[(size_t)ED*NE/2];
__device__ unsigned g_qh [(size_t)NBH*SQL*ED/2], g_ql [(size_t)NBH*SQL*ED/2];
__device__ unsigned g_kh [(size_t)NBH*SQL*ED/2], g_kl [(size_t)NBH*SQL*ED/2];
__device__ unsigned g_vh [(size_t)NBH*SQL*ED/2], g_vl [(size_t)NBH*SQL*ED/2];
__device__ unsigned g_ph [(size_t)NBH*SQL*SQL/2], g_pl [(size_t)NBH*SQL*SQL/2];
__device__ unsigned g_ah [(size_t)TOK*NE/2],  g_al [(size_t)TOK*NE/2];
__device__ float    g_scores[(size_t)NBH*SQL*SQL];

#define BM 128
#define BN 64          /* block tile 128x64; warp tile 32x32 */
#define BK 16
#define STRIDE 12      /* A/B(NT) smem rows: 8 used u32 + 4 pad */
#define STG_B 18432u   /* NT stage: A hi/lo 2x6144 + B hi/lo 2x3072 */
#define BPITCH 144u    /* pv B tile row pitch (128 B data + 16 pad) */
#define STG_PV 16896u  /* pv stage: A hi/lo 2x6144 + B hi/lo 2x2304 */
#define NPIPE 4
#define SMEM_SZ (NPIPE*18432)   /* 72 KB per CTA -> 3 CTAs/SM */

__device__ __forceinline__ unsigned smem_u32(const void* p) {
    unsigned a;
    asm("{ .reg .u64 t; cvta.to.shared.u64 t, %1; cvt.u32.u64 %0, t; }" : "=r"(a) : "l"(p));
    return a;
}

__device__ __forceinline__ void split2(float a, float b, unsigned &h, unsigned &l) {
    __nv_bfloat16 ah = __float2bfloat16(a), bh = __float2bfloat16(b);
    float ar = a - __bfloat162float(ah);
    float br = b - __bfloat162float(bh);
    __nv_bfloat16 al = __float2bfloat16(ar), bl = __float2bfloat16(br);
    h = (unsigned)__bfloat16_as_ushort(ah) | ((unsigned)__bfloat16_as_ushort(bh) << 16);
    l = (unsigned)__bfloat16_as_ushort(al) | ((unsigned)__bfloat16_as_ushort(bl) << 16);
}

#define MMA_BF16(C, A0, A1, A2, A3, B0, B1)                                      \
    asm volatile("mma.sync.aligned.m16n8k16.row.col.f32.bf16.bf16.f32 "          \
        "{%0,%1,%2,%3}, {%4,%5,%6,%7}, {%8,%9}, {%0,%1,%2,%3};"                  \
        : "+f"((C)[0]), "+f"((C)[1]), "+f"((C)[2]), "+f"((C)[3])                  \
        : "r"(A0), "r"(A1), "r"(A2), "r"(A3), "r"(B0), "r"(B1))

__device__ __forceinline__ void ldsm4(unsigned addr, unsigned r[4]) {
    asm volatile("ldmatrix.sync.aligned.m8n8.x4.shared.b16 {%0,%1,%2,%3}, [%4];"
        : "=r"(r[0]), "=r"(r[1]), "=r"(r[2]), "=r"(r[3]) : "r"(addr));
}
__device__ __forceinline__ void ldsm4t(unsigned addr, unsigned r[4]) {
    asm volatile("ldmatrix.sync.aligned.m8n8.x4.trans.shared.b16 {%0,%1,%2,%3}, [%4];"
        : "=r"(r[0]), "=r"(r[1]), "=r"(r[2]), "=r"(r[3]) : "r"(addr));
}

// NT stage: B tile rows = n (8 u32 along k), non-trans ldsm. Warp tile 32x32.
__device__ __forceinline__ void compute_stage(
    unsigned Ah, unsigned Al, unsigned Bh, unsigned Bl,
    int wm, int wn, int lane, float acc[2][4][4])
{
    const int lrow = (lane & 7) | (((lane >> 3) & 1) << 3);
    const int lcw  = (lane >> 4) * 4;
    const unsigned aoff = (unsigned)(((wm*32 + lrow) * STRIDE + lcw) * 4);
    const unsigned boff = (unsigned)(((wn*32 + lrow) * STRIDE + lcw) * 4);

    unsigned ah[2][4], al[2][4];
    #pragma unroll
    for (int mt = 0; mt < 2; mt++) {
        ldsm4(Ah + aoff + (unsigned)(mt*16*STRIDE*4), ah[mt]);
        ldsm4(Al + aoff + (unsigned)(mt*16*STRIDE*4), al[mt]);
    }
    #pragma unroll
    for (int ntp = 0; ntp < 2; ntp++) {
        unsigned bh[4], bl[4];
        ldsm4(Bh + boff + (unsigned)(ntp*16*STRIDE*4), bh);
        ldsm4(Bl + boff + (unsigned)(ntp*16*STRIDE*4), bl);
        #pragma unroll
        for (int sub = 0; sub < 2; sub++) {
            const int nt = ntp*2 + sub;
            #pragma unroll
            for (int mt = 0; mt < 2; mt++) {
                MMA_BF16(acc[mt][nt], ah[mt][0], ah[mt][1], ah[mt][2], ah[mt][3], bh[sub], bh[2+sub]);
                MMA_BF16(acc[mt][nt], ah[mt][0], ah[mt][1], ah[mt][2], ah[mt][3], bl[sub], bl[2+sub]);
                MMA_BF16(acc[mt][nt], al[mt][0], al[mt][1], al[mt][2], al[mt][3], bh[sub], bh[2+sub]);
            }
        }
    }
}

// PV stage: B tile rows = k (16 rows x 128B bf16 along n=d, pitch 144B),
// trans ldsm. Register ordering arranged to keep (b[sub], b[2+sub]) pattern:
// lane -> mi=lane>>3; n_half=mi&1, k_half=mi>>1; row=k_half*8+(lane&7).
__device__ __forceinline__ void compute_stage_pv(
    unsigned Ah, unsigned Al, unsigned Bh, unsigned Bl,
    int wm, int wn, int lane, float acc[2][4][4])
{
    const int lrow = (lane & 7) | (((lane >> 3) & 1) << 3);
    const int lcw  = (lane >> 4) * 4;
    const unsigned aoff = (unsigned)(((wm*32 + lrow) * STRIDE + lcw) * 4);
    const int bk  = ((lane >> 4) & 1) * 8 + (lane & 7);
    const int bnh = (lane >> 3) & 1;
    const unsigned boff = (unsigned)(bk * BPITCH + (unsigned)(wn*64 + bnh*16));

    unsigned ah[2][4], al[2][4];
    #pragma unroll
    for (int mt = 0; mt < 2; mt++) {
        ldsm4(Ah + aoff + (unsigned)(mt*16*STRIDE*4), ah[mt]);
        ldsm4(Al + aoff + (unsigned)(mt*16*STRIDE*4), al[mt]);
    }
    #pragma unroll
    for (int ntp = 0; ntp < 2; ntp++) {
        unsigned bh[4], bl[4];
        ldsm4t(Bh + boff + (unsigned)(ntp*32), bh);
        ldsm4t(Bl + boff + (unsigned)(ntp*32), bl);
        #pragma unroll
        for (int sub = 0; sub < 2; sub++) {
            const int nt = ntp*2 + sub;
            #pragma unroll
            for (int mt = 0; mt < 2; mt++) {
                MMA_BF16(acc[mt][nt], ah[mt][0], ah[mt][1], ah[mt][2], ah[mt][3], bh[sub], bh[2+sub]);
                MMA_BF16(acc[mt][nt], ah[mt][0], ah[mt][1], ah[mt][2], ah[mt][3], bl[sub], bl[2+sub]);
                MMA_BF16(acc[mt][nt], al[mt][0], al[mt][1], al[mt][2], al[mt][3], bh[sub], bh[2+sub]);
            }
        }
    }
}

#define CPA(dst, src) \
    asm volatile("cp.async.cg.shared.global [%0], [%1], 16;" :: "r"(dst), "l"(src))

// NT stage issue (A 128x16 all threads, B 64x16 t<128)
#define ISSUE_STAGE(s, b) {                                                       \
    unsigned d_ = smb + (unsigned)(b)*STG_B + (unsigned)(lr*48 + half*16);        \
    CPA(d_,         aH + (size_t)(s)*8);                                          \
    CPA(d_ + 6144u, aL + (size_t)(s)*8);                                          \
    if (t < 128) {                                                                \
        unsigned e_ = smb + (unsigned)(b)*STG_B + 12288u + (unsigned)(lr*48 + half*16); \
        CPA(e_,         bH + (size_t)(s)*8);                                      \
        CPA(e_ + 3072u, bL + (size_t)(s)*8);                                      \
    }                                                                             \
    asm volatile("cp.async.commit_group;" ::: "memory"); }

#define GEMM_LOOP(NS_) {                                                          \
    ISSUE_STAGE(0, 0);                                                            \
    ISSUE_STAGE(1, 1);                                                            \
    ISSUE_STAGE(2, 2);                                                            \
    for (int i = 0; i < (NS_); i++) {                                             \
        const int rem = (NS_) - 1 - i;                                            \
        if (rem >= 2)      { asm volatile("cp.async.wait_group 2;" ::: "memory"); }\
        else if (rem == 1) { asm volatile("cp.async.wait_group 1;" ::: "memory"); }\
        else               { asm volatile("cp.async.wait_group 0;" ::: "memory"); }\
        __syncthreads();                                                          \
        const unsigned bb = smb + (unsigned)(i & 3) * STG_B;                      \
        compute_stage(bb, bb + 6144u, bb + 12288u, bb + 15360u, wm, wn, lane, acc);\
        if (i + 3 < (NS_)) ISSUE_STAGE(i + 3, (i + 3) & 3);                       \
    } }

// PV stage issue: A as NT; B = V rows s (16 per stage), pitch 144B, t<128.
#define ISSUE_PV(s, b) {                                                          \
    unsigned d_ = smb + (unsigned)(b)*STG_PV + (unsigned)(lr*48 + half*16);       \
    CPA(d_,         aH + (size_t)(s)*8);                                          \
    CPA(d_ + 6144u, aL + (size_t)(s)*8);                                          \
    if (t < 128) {                                                                \
        unsigned e_ = smb + (unsigned)(b)*STG_PV + 12288u                         \
                    + (unsigned)((t>>3)*BPITCH + (t&7)*16);                       \
        CPA(e_,         vbh + (size_t)(s)*16*128);                                \
        CPA(e_ + 2304u, vbl + (size_t)(s)*16*128);                                \
    }                                                                             \
    asm volatile("cp.async.commit_group;" ::: "memory"); }

#define GEMM_LOOP_PV(NS_) {                                                       \
    ISSUE_PV(0, 0);                                                               \
    ISSUE_PV(1, 1);                                                               \
    ISSUE_PV(2, 2);                                                               \
    for (int i = 0; i < (NS_); i++) {                                             \
        const int rem = (NS_) - 1 - i;                                            \
        if (rem >= 2)      { asm volatile("cp.async.wait_group 2;" ::: "memory"); }\
        else if (rem == 1) { asm volatile("cp.async.wait_group 1;" ::: "memory"); }\
        else               { asm volatile("cp.async.wait_group 0;" ::: "memory"); }\
        __syncthreads();                                                          \
        const unsigned bb = smb + (unsigned)(i & 3) * STG_PV;                     \
        compute_stage_pv(bb, bb + 6144u, bb + 12288u, bb + 14592u, wm, wn, lane, acc);\
        if (i + 3 < (NS_)) ISSUE_PV(i + 3, (i + 3) & 3);                          \
    } }

// ---------------------------------------------------------------------------
// Kernel 0: pre-split fp32 -> hi/lo packed bf16 pairs
// ---------------------------------------------------------------------------
__global__ void __launch_bounds__(256) split_pairs(const float* __restrict__ src,
                                                   unsigned* __restrict__ H,
                                                   unsigned* __restrict__ L, int nwords) {
    int i = blockIdx.x * 256 + threadIdx.x;
    if (i < nwords) {
        float2 v = ((const float2*)src)[i];
        unsigned h, l;
        split2(v.x, v.y, h, l);
        H[i] = h; L[i] = l;
    }
}

// Q/K/V epilogue writer: raw-view remap baked in. row = global token, col in [0,2048)
__device__ __forceinline__ void write_qk(unsigned* H, unsigned* L, int row, int col,
                                         float v0, float v1) {
    int b = row >> 10, sp = row & 1023;
    int h = sp >> 7, s = ((sp & 127) << 3) + (col >> 8), d = col & 255;
    size_t idx = ((((size_t)(b*8 + h)) * SQL + s) << 7) + (d >> 1);
    unsigned hh, ll;
    split2(v0, v1, hh, ll);
    H[idx] = hh; L[idx] = ll;
}

// ---------------------------------------------------------------------------
// Kernel 1: proj = x @ w_attn^T + b_attn; scatters Q,K,V split-bf16 (uniform)
// ---------------------------------------------------------------------------
__global__ void __launch_bounds__(256, 3) proj_gemm(const float* __restrict__ bias) {
    extern __shared__ unsigned smd[];
    const unsigned smb = smem_u32(smd);
    const int m0 = blockIdx.y * BM, n0 = blockIdx.x * BN;
    const int t = threadIdx.x, lane = t & 31, w = t >> 5;
    const int wm = w >> 1, wn = w & 1;
    const int lr = t >> 1, half = t & 1;
    const unsigned* aH = g_xh  + (size_t)(m0 + lr) * 128 + half*4;
    const unsigned* aL = g_xl  + (size_t)(m0 + lr) * 128 + half*4;
    const unsigned* bH = g_wah + (size_t)(n0 + lr) * 128 + half*4;
    const unsigned* bL = g_wal + (size_t)(n0 + lr) * 128 + half*4;
    float acc[2][4][4] = {};
    GEMM_LOOP(ED/BK);

    const int g = lane >> 2, qq = lane & 3;
    #pragma unroll
    for (int mt = 0; mt < 2; mt++) {
        int row = m0 + wm*32 + mt*16 + g;
        #pragma unroll
        for (int nt = 0; nt < 4; nt++) {
            int col = n0 + wn*32 + nt*8 + qq*2;
            float bv0 = bias[col], bv1 = bias[col+1];
            float p0 = acc[mt][nt][0] + bv0, p1 = acc[mt][nt][1] + bv1;
            float p2 = acc[mt][nt][2] + bv0, p3 = acc[mt][nt][3] + bv1;
            unsigned *H, *L; int c;
            if (col < NE)          { H = g_qh; L = g_ql; c = col; }
            else if (col < 2*NE)   { H = g_kh; L = g_kl; c = col - NE; }
            else                   { H = g_vh; L = g_vl; c = col - 2*NE; }
            write_qk(H, L, row,   c, p0, p1);
            write_qk(H, L, row+8, c, p2, p3);
        }
    }
}

// ---------------------------------------------------------------------------
// Kernel 2: scores = (Q·K^T)/16; skip tiles fully above diagonal
// ---------------------------------------------------------------------------
__global__ void __launch_bounds__(256, 3) score_gemm() {
    const int q0 = blockIdx.y * BM, k0 = blockIdx.x * BN;
    if (k0 > q0 + (BM - 1)) return;
    const int bh = blockIdx.z;
    extern __shared__ unsigned smd[];
    const unsigned smb = smem_u32(smd);
    const int t = threadIdx.x, lane = t & 31, w = t >> 5;
    const int wm = w >> 1, wn = w & 1;
    const int lr = t >> 1, half = t & 1;
    const unsigned* aH = g_qh + ((size_t)bh * SQL + q0 + lr) * 128 + half*4;
    const unsigned* aL = g_ql + ((size_t)bh * SQL + q0 + lr) * 128 + half*4;
    const unsigned* bH = g_kh + ((size_t)bh * SQL + k0 + lr) * 128 + half*4;
    const unsigned* bL = g_kl + ((size_t)bh * SQL + k0 + lr) * 128 + half*4;
    float acc[2][4][4] = {};
    GEMM_LOOP(ED/BK);

    float* S = g_scores + (size_t)bh * SQL * SQL;
    const int g = lane >> 2, qq = lane & 3;
    #pragma unroll
    for (int mt = 0; mt < 2; mt++) {
        int row = q0 + wm*32 + mt*16 + g;
        #pragma unroll
        for (int nt = 0; nt < 4; nt++) {
            int col = k0 + wn*32 + nt*8 + qq*2;
            float* d0 = S + (size_t)row * SQL + col;
            float* d1 = S + (size_t)(row+8) * SQL + col;
            *(float2*)d0 = make_float2(acc[mt][nt][0]*0.0625f, acc[mt][nt][1]*0.0625f);
            *(float2*)d1 = make_float2(acc[mt][nt][2]*0.0625f, acc[mt][nt][3]*0.0625f);
        }
    }
}

// ---------------------------------------------------------------------------
// Kernel 3: causal softmax; writes P split-bf16 packed pairs along k
// ---------------------------------------------------------------------------
__global__ void __launch_bounds__(128) softmax_rows() {
    const int row = blockIdx.x;
    const int q = row & (SQL - 1);
    const float* r = g_scores + (size_t)row * SQL;
    const int t = threadIdx.x;
    const int k0 = t * 8;
    float v[8];
    float4 x0 = *(const float4*)(r + k0);
    float4 x1 = *(const float4*)(r + k0 + 4);
    v[0]=x0.x; v[1]=x0.y; v[2]=x0.z; v[3]=x0.w;
    v[4]=x1.x; v[5]=x1.y; v[6]=x1.z; v[7]=x1.w;
    float mx = -1e30f;
    #pragma unroll
    for (int i = 0; i < 8; i++) {
        v[i] = (k0 + i <= q) ? v[i] : -1e30f;
        mx = fmaxf(mx, v[i]);
    }
    __shared__ float redm[4], reds[4];
    #pragma unroll
    for (int o = 16; o > 0; o >>= 1) mx = fmaxf(mx, __shfl_xor_sync(0xffffffffu, mx, o));
    if ((t & 31) == 0) redm[t >> 5] = mx;
    __syncthreads();
    mx = fmaxf(fmaxf(redm[0], redm[1]), fmaxf(redm[2], redm[3]));
    float sum = 0.f;
    #pragma unroll
    for (int i = 0; i < 8; i++) {
        v[i] = (k0 + i <= q) ? expf(v[i] - mx) : 0.f;
        sum += v[i];
    }
    #pragma unroll
    for (int o = 16; o > 0; o >>= 1) sum += __shfl_xor_sync(0xffffffffu, sum, o);
    if ((t & 31) == 0) reds[t >> 5] = sum;
    __syncthreads();
    sum = reds[0] + reds[1] + reds[2] + reds[3];
    float inv = 1.f / sum;
    unsigned hh[4], ll[4];
    #pragma unroll
    for (int j = 0; j < 4; j++)
        split2(v[2*j] * inv, v[2*j+1] * inv, hh[j], ll[j]);
    *(uint4*)(g_ph + (size_t)row * 512 + t*4) = make_uint4(hh[0], hh[1], hh[2], hh[3]);
    *(uint4*)(g_pl + (size_t)row * 512 + t*4) = make_uint4(ll[0], ll[1], ll[2], ll[3]);
}

// ---------------------------------------------------------------------------
// Kernel 4: O = P @ V (V natural layout, B frags via ldsm.trans); causal trunc
// ---------------------------------------------------------------------------
__global__ void __launch_bounds__(256, 3) pv_gemm() {
    const int bh = blockIdx.z;
    const int q0 = (int)(gridDim.y - 1 - blockIdx.y) * BM;   // heavy tiles first
    const int n0 = blockIdx.x * BN;
    extern __shared__ unsigned smd[];
    const unsigned smb = smem_u32(smd);
    const int t = threadIdx.x, lane = t & 31, w = t >> 5;
    const int wm = w >> 1, wn = w & 1;
    const int lr = t >> 1, half = t & 1;
    const int NS = (q0 + BM) / BK;
    const unsigned* aH = g_ph + ((size_t)bh * SQL + q0 + lr) * 512 + half*4;
    const unsigned* aL = g_pl + ((size_t)bh * SQL + q0 + lr) * 512 + half*4;
    const unsigned* vbh = g_vh + ((size_t)bh * SQL + (t>>3)) * 128 + (n0>>1) + (t&7)*4;
    const unsigned* vbl = g_vl + ((size_t)bh * SQL + (t>>3)) * 128 + (n0>>1) + (t&7)*4;
    float acc[2][4][4] = {};
    GEMM_LOOP_PV(NS);

    const int g = lane >> 2, qq = lane & 3;
    #pragma unroll
    for (int mt = 0; mt < 2; mt++) {
        int row = q0 + wm*32 + mt*16 + g;
        #pragma unroll
        for (int nt = 0; nt < 4; nt++) {
            int col = n0 + wn*32 + nt*8 + qq*2;
            size_t i0 = ((size_t)bh * SQL + row) * 128 + (col >> 1);
            size_t i1 = ((size_t)bh * SQL + row + 8) * 128 + (col >> 1);
            unsigned hh, ll;
            split2(acc[mt][nt][0], acc[mt][nt][1], hh, ll);
            g_ah[i0] = hh; g_al[i0] = ll;
            split2(acc[mt][nt][2], acc[mt][nt][3], hh, ll);
            g_ah[i1] = hh; g_al[i1] = ll;
        }
    }
}

// ---------------------------------------------------------------------------
// Kernel 5: out = attn_flat @ w_out^T + b_out (fp32 output)
// ---------------------------------------------------------------------------
__global__ void __launch_bounds__(256, 3) out_gemm(const float* __restrict__ bias,
                                                   float* __restrict__ C) {
    extern __shared__ unsigned smd[];
    const unsigned smb = smem_u32(smd);
    const int m0 = blockIdx.y * BM, n0 = blockIdx.x * BN;
    const int t = threadIdx.x, lane = t & 31, w = t >> 5;
    const int wm = w >> 1, wn = w & 1;
    const int lr = t >> 1, half = t & 1;
    const unsigned* aH = g_ah  + (size_t)(m0 + lr) * 1024 + half*4;
    const unsigned* aL = g_al  + (size_t)(m0 + lr) * 1024 + half*4;
    const unsigned* bH = g_woh + (size_t)(n0 + lr) * 1024 + half*4;
    const unsigned* bL = g_wol + (size_t)(n0 + lr) * 1024 + half*4;
    float acc[2][4][4] = {};
    GEMM_LOOP(NE/BK);

    const int g = lane >> 2, qq = lane & 3;
    #pragma unroll
    for (int mt = 0; mt < 2; mt++) {
        int row = m0 + wm*32 + mt*16 + g;
        #pragma unroll
        for (int nt = 0; nt < 4; nt++) {
            int col = n0 + wn*32 + nt*8 + qq*2;
            float bv0 = bias[col], bv1 = bias[col+1];
            float* d0 = C + (size_t)row * ED + col;
            float* d1 = C + (size_t)(row+8) * ED + col;
            *(float2*)d0 = make_float2(acc[mt][nt][0] + bv0, acc[mt][nt][1] + bv1);
            *(float2*)d1 = make_float2(acc[mt][nt][2] + bv0, acc[mt][nt][3] + bv1);
        }
    }
}

extern "C" void kernel_launch(void* const* d_in, const int* in_sizes, int n_in,
                              void* d_out, int out_size) {
    const float* x      = (const float*)d_in[0];
    const float* w_attn = (const float*)d_in[1];
    const float* b_attn = (const float*)d_in[2];
    const float* w_out  = (const float*)d_in[3];
    const float* b_out  = (const float*)d_in[4];
    float* out = (float*)d_out;

    unsigned *xh, *xl, *wah, *wal, *woh, *wol;
    cudaGetSymbolAddress((void**)&xh,  g_xh);
    cudaGetSymbolAddress((void**)&xl,  g_xl);
    cudaGetSymbolAddress((void**)&wah, g_wah);
    cudaGetSymbolAddress((void**)&wal, g_wal);
    cudaGetSymbolAddress((void**)&woh, g_woh);
    cudaGetSymbolAddress((void**)&wol, g_wol);

    cudaFuncSetAttribute(proj_gemm,  cudaFuncAttributeMaxDynamicSharedMemorySize, SMEM_SZ);
    cudaFuncSetAttribute(score_gemm, cudaFuncAttributeMaxDynamicSharedMemorySize, SMEM_SZ);
    cudaFuncSetAttribute(pv_gemm,    cudaFuncAttributeMaxDynamicSharedMemorySize, SMEM_SZ);
    cudaFuncSetAttribute(out_gemm,   cudaFuncAttributeMaxDynamicSharedMemorySize, SMEM_SZ);

    const int NX = TOK*ED/2, NWA = QKV*ED/2, NWO = ED*NE/2;
    split_pairs<<<(NX  + 255)/256, 256>>>(x,      xh,  xl,  NX);
    split_pairs<<<(NWA + 255)/256, 256>>>(w_attn, wah, wal, NWA);
    split_pairs<<<(NWO + 255)/256, 256>>>(w_out,  woh, wol, NWO);

    proj_gemm<<<dim3(QKV/BN, TOK/BM), 256, SMEM_SZ>>>(b_attn);
    score_gemm<<<dim3(SQL/BN, SQL/BM, NBH), 256, SMEM_SZ>>>();
    softmax_rows<<<NBH*SQL, 128>>>();
    pv_gemm<<<dim3(ED/BN, SQL/BM, NBH), 256, NPIPE*STG_PV>>>();
    out_gemm<<<dim3(ED/BN, TOK/BM), 256, SMEM_SZ>>>(b_out, out);
}

// round 12
// speedup vs baseline: 1.3857x; 1.0345x over previous
#include <cuda_runtime.h>
#include <cuda_bf16.h>
#include <math.h>
#include <stdint.h>

#define NHH 8
#define ED 256
#define SQL 1024
#define BSZ 4
#define QKV (NHH*3*ED)   /* 6144 */
#define NE  (NHH*ED)     /* 2048 */
#define TOK (BSZ*SQL)    /* 4096 */
#define NBH (BSZ*NHH)    /* 32 */

// ---------------------------------------------------------------------------
// Device-global scratch. hi/lo split-bf16: packed u32 = (elem2i, elem2i+1).
// Q, K, V all stored natural [bh][s][d/2] (raw-view remap applied at write).
// ---------------------------------------------------------------------------
__device__ unsigned g_xh [(size_t)TOK*ED/2],  g_xl [(size_t)TOK*ED/2];
__device__ unsigned g_wah[(size_t)QKV*ED/2],  g_wal[(size_t)QKV*ED/2];
__device__ unsigned g_woh[(size_t)ED*NE/2],   g_wol[(size_t)ED*NE/2];
__device__ unsigned g_qh [(size_t)NBH*SQL*ED/2], g_ql [(size_t)NBH*SQL*ED/2];
__device__ unsigned g_kh [(size_t)NBH*SQL*ED/2], g_kl [(size_t)NBH*SQL*ED/2];
__device__ unsigned g_vh [(size_t)NBH*SQL*ED/2], g_vl [(size_t)NBH*SQL*ED/2];
__device__ unsigned g_ph [(size_t)NBH*SQL*SQL/2], g_pl [(size_t)NBH*SQL*SQL/2];
__device__ unsigned g_ah [(size_t)TOK*NE/2],  g_al [(size_t)TOK*NE/2];
__device__ float    g_scores[(size_t)NBH*SQL*SQL];
__device__ float    g_op0[(size_t)TOK*ED], g_op1[(size_t)TOK*ED];  // out split-K partials

#define BM 128
#define BN 64          /* block tile 128x64; warp tile 32x32 */
#define BK 16
#define STRIDE 12      /* A/B(NT) smem rows: 8 used u32 + 4 pad */
#define STG_B 18432u   /* NT stage: A hi/lo 2x6144 + B hi/lo 2x3072 */
#define BPITCH 144u    /* pv B tile row pitch (128 B data + 16 pad) */
#define STG_PV 16896u  /* pv stage: A hi/lo 2x6144 + B hi/lo 2x2304 */
#define NPIPE 4
#define SMEM_SZ (NPIPE*18432)   /* 72 KB per CTA -> 3 CTAs/SM */

__device__ __forceinline__ unsigned smem_u32(const void* p) {
    unsigned a;
    asm("{ .reg .u64 t; cvta.to.shared.u64 t, %1; cvt.u32.u64 %0, t; }" : "=r"(a) : "l"(p));
    return a;
}

__device__ __forceinline__ void split2(float a, float b, unsigned &h, unsigned &l) {
    __nv_bfloat16 ah = __float2bfloat16(a), bh = __float2bfloat16(b);
    float ar = a - __bfloat162float(ah);
    float br = b - __bfloat162float(bh);
    __nv_bfloat16 al = __float2bfloat16(ar), bl = __float2bfloat16(br);
    h = (unsigned)__bfloat16_as_ushort(ah) | ((unsigned)__bfloat16_as_ushort(bh) << 16);
    l = (unsigned)__bfloat16_as_ushort(al) | ((unsigned)__bfloat16_as_ushort(bl) << 16);
}

#define MMA_BF16(C, A0, A1, A2, A3, B0, B1)                                      \
    asm volatile("mma.sync.aligned.m16n8k16.row.col.f32.bf16.bf16.f32 "          \
        "{%0,%1,%2,%3}, {%4,%5,%6,%7}, {%8,%9}, {%0,%1,%2,%3};"                  \
        : "+f"((C)[0]), "+f"((C)[1]), "+f"((C)[2]), "+f"((C)[3])                  \
        : "r"(A0), "r"(A1), "r"(A2), "r"(A3), "r"(B0), "r"(B1))

__device__ __forceinline__ void ldsm4(unsigned addr, unsigned r[4]) {
    asm volatile("ldmatrix.sync.aligned.m8n8.x4.shared.b16 {%0,%1,%2,%3}, [%4];"
        : "=r"(r[0]), "=r"(r[1]), "=r"(r[2]), "=r"(r[3]) : "r"(addr));
}
__device__ __forceinline__ void ldsm4t(unsigned addr, unsigned r[4]) {
    asm volatile("ldmatrix.sync.aligned.m8n8.x4.trans.shared.b16 {%0,%1,%2,%3}, [%4];"
        : "=r"(r[0]), "=r"(r[1]), "=r"(r[2]), "=r"(r[3]) : "r"(addr));
}

// NT stage: B tile rows = n (8 u32 along k), non-trans ldsm. Warp tile 32x32.
__device__ __forceinline__ void compute_stage(
    unsigned Ah, unsigned Al, unsigned Bh, unsigned Bl,
    int wm, int wn, int lane, float acc[2][4][4])
{
    const int lrow = (lane & 7) | (((lane >> 3) & 1) << 3);
    const int lcw  = (lane >> 4) * 4;
    const unsigned aoff = (unsigned)(((wm*32 + lrow) * STRIDE + lcw) * 4);
    const unsigned boff = (unsigned)(((wn*32 + lrow) * STRIDE + lcw) * 4);

    unsigned ah[2][4], al[2][4];
    #pragma unroll
    for (int mt = 0; mt < 2; mt++) {
        ldsm4(Ah + aoff + (unsigned)(mt*16*STRIDE*4), ah[mt]);
        ldsm4(Al + aoff + (unsigned)(mt*16*STRIDE*4), al[mt]);
    }
    #pragma unroll
    for (int ntp = 0; ntp < 2; ntp++) {
        unsigned bh[4], bl[4];
        ldsm4(Bh + boff + (unsigned)(ntp*16*STRIDE*4), bh);
        ldsm4(Bl + boff + (unsigned)(ntp*16*STRIDE*4), bl);
        #pragma unroll
        for (int sub = 0; sub < 2; sub++) {
            const int nt = ntp*2 + sub;
            #pragma unroll
            for (int mt = 0; mt < 2; mt++) {
                MMA_BF16(acc[mt][nt], ah[mt][0], ah[mt][1], ah[mt][2], ah[mt][3], bh[sub], bh[2+sub]);
                MMA_BF16(acc[mt][nt], ah[mt][0], ah[mt][1], ah[mt][2], ah[mt][3], bl[sub], bl[2+sub]);
                MMA_BF16(acc[mt][nt], al[mt][0], al[mt][1], al[mt][2], al[mt][3], bh[sub], bh[2+sub]);
            }
        }
    }
}

// PV stage: B tile rows = k (16 rows x 128B bf16 along n=d, pitch 144B), trans ldsm.
__device__ __forceinline__ void compute_stage_pv(
    unsigned Ah, unsigned Al, unsigned Bh, unsigned Bl,
    int wm, int wn, int lane, float acc[2][4][4])
{
    const int lrow = (lane & 7) | (((lane >> 3) & 1) << 3);
    const int lcw  = (lane >> 4) * 4;
    const unsigned aoff = (unsigned)(((wm*32 + lrow) * STRIDE + lcw) * 4);
    const int bk  = ((lane >> 4) & 1) * 8 + (lane & 7);
    const int bnh = (lane >> 3) & 1;
    const unsigned boff = (unsigned)(bk * BPITCH + (unsigned)(wn*64 + bnh*16));

    unsigned ah[2][4], al[2][4];
    #pragma unroll
    for (int mt = 0; mt < 2; mt++) {
        ldsm4(Ah + aoff + (unsigned)(mt*16*STRIDE*4), ah[mt]);
        ldsm4(Al + aoff + (unsigned)(mt*16*STRIDE*4), al[mt]);
    }
    #pragma unroll
    for (int ntp = 0; ntp < 2; ntp++) {
        unsigned bh[4], bl[4];
        ldsm4t(Bh + boff + (unsigned)(ntp*32), bh);
        ldsm4t(Bl + boff + (unsigned)(ntp*32), bl);
        #pragma unroll
        for (int sub = 0; sub < 2; sub++) {
            const int nt = ntp*2 + sub;
            #pragma unroll
            for (int mt = 0; mt < 2; mt++) {
                MMA_BF16(acc[mt][nt], ah[mt][0], ah[mt][1], ah[mt][2], ah[mt][3], bh[sub], bh[2+sub]);
                MMA_BF16(acc[mt][nt], ah[mt][0], ah[mt][1], ah[mt][2], ah[mt][3], bl[sub], bl[2+sub]);
                MMA_BF16(acc[mt][nt], al[mt][0], al[mt][1], al[mt][2], al[mt][3], bh[sub], bh[2+sub]);
            }
        }
    }
}

#define CPA(dst, src) \
    asm volatile("cp.async.cg.shared.global [%0], [%1], 16;" :: "r"(dst), "l"(src))

#define ISSUE_STAGE(s, b) {                                                       \
    unsigned d_ = smb + (unsigned)(b)*STG_B + (unsigned)(lr*48 + half*16);        \
    CPA(d_,         aH + (size_t)(s)*8);                                          \
    CPA(d_ + 6144u, aL + (size_t)(s)*8);                                          \
    if (t < 128) {                                                                \
        unsigned e_ = smb + (unsigned)(b)*STG_B + 12288u + (unsigned)(lr*48 + half*16); \
        CPA(e_,         bH + (size_t)(s)*8);                                      \
        CPA(e_ + 3072u, bL + (size_t)(s)*8);                                      \
    }                                                                             \
    asm volatile("cp.async.commit_group;" ::: "memory"); }

#define GEMM_LOOP(NS_) {                                                          \
    ISSUE_STAGE(0, 0);                                                            \
    ISSUE_STAGE(1, 1);                                                            \
    ISSUE_STAGE(2, 2);                                                            \
    for (int i = 0; i < (NS_); i++) {                                             \
        const int rem = (NS_) - 1 - i;                                            \
        if (rem >= 2)      { asm volatile("cp.async.wait_group 2;" ::: "memory"); }\
        else if (rem == 1) { asm volatile("cp.async.wait_group 1;" ::: "memory"); }\
        else               { asm volatile("cp.async.wait_group 0;" ::: "memory"); }\
        __syncthreads();                                                          \
        const unsigned bb = smb + (unsigned)(i & 3) * STG_B;                      \
        compute_stage(bb, bb + 6144u, bb + 12288u, bb + 15360u, wm, wn, lane, acc);\
        if (i + 3 < (NS_)) ISSUE_STAGE(i + 3, (i + 3) & 3);                       \
    } }

#define ISSUE_PV(s, b) {                                                          \
    unsigned d_ = smb + (unsigned)(b)*STG_PV + (unsigned)(lr*48 + half*16);       \
    CPA(d_,         aH + (size_t)(s)*8);                                          \
    CPA(d_ + 6144u, aL + (size_t)(s)*8);                                          \
    if (t < 128) {                                                                \
        unsigned e_ = smb + (unsigned)(b)*STG_PV + 12288u                         \
                    + (unsigned)((t>>3)*BPITCH + (t&7)*16);                       \
        CPA(e_,         vbh + (size_t)(s)*16*128);                                \
        CPA(e_ + 2304u, vbl + (size_t)(s)*16*128);                                \
    }                                                                             \
    asm volatile("cp.async.commit_group;" ::: "memory"); }

#define GEMM_LOOP_PV(NS_) {                                                       \
    ISSUE_PV(0, 0);                                                               \
    ISSUE_PV(1, 1);                                                               \
    ISSUE_PV(2, 2);                                                               \
    for (int i = 0; i < (NS_); i++) {                                             \
        const int rem = (NS_) - 1 - i;                                            \
        if (rem >= 2)      { asm volatile("cp.async.wait_group 2;" ::: "memory"); }\
        else if (rem == 1) { asm volatile("cp.async.wait_group 1;" ::: "memory"); }\
        else               { asm volatile("cp.async.wait_group 0;" ::: "memory"); }\
        __syncthreads();                                                          \
        const unsigned bb = smb + (unsigned)(i & 3) * STG_PV;                     \
        compute_stage_pv(bb, bb + 6144u, bb + 12288u, bb + 14592u, wm, wn, lane, acc);\
        if (i + 3 < (NS_)) ISSUE_PV(i + 3, (i + 3) & 3);                          \
    } }

// ---------------------------------------------------------------------------
// Kernel 0: pre-split all three fp32 operands -> hi/lo packed bf16 (one launch)
// ---------------------------------------------------------------------------
#define NXW  (TOK*ED/2)
#define NWAW (QKV*ED/2)
#define NWOW (ED*NE/2)
__global__ void __launch_bounds__(256) split_all(const float* __restrict__ x,
                                                 const float* __restrict__ wa,
                                                 const float* __restrict__ wo) {
    int i = blockIdx.x * 256 + threadIdx.x;
    const float* src; unsigned *H, *L; int j = i;
    if (j < NXW)              { src = x;  H = g_xh;  L = g_xl; }
    else if ((j -= NXW) < NWAW) { src = wa; H = g_wah; L = g_wal; }
    else if ((j -= NWAW) < NWOW){ src = wo; H = g_woh; L = g_wol; }
    else return;
    float2 v = ((const float2*)src)[j];
    unsigned h, l;
    split2(v.x, v.y, h, l);
    H[j] = h; L[j] = l;
}

// Q/K/V epilogue writer: raw-view remap baked in. row = global token, col in [0,2048)
__device__ __forceinline__ void write_qk(unsigned* H, unsigned* L, int row, int col,
                                         float v0, float v1) {
    int b = row >> 10, sp = row & 1023;
    int h = sp >> 7, s = ((sp & 127) << 3) + (col >> 8), d = col & 255;
    size_t idx = ((((size_t)(b*8 + h)) * SQL + s) << 7) + (d >> 1);
    unsigned hh, ll;
    split2(v0, v1, hh, ll);
    H[idx] = hh; L[idx] = ll;
}

// ---------------------------------------------------------------------------
// Kernel 1: proj = x @ w_attn^T + b_attn; scatters Q,K,V split-bf16
// ---------------------------------------------------------------------------
__global__ void __launch_bounds__(256, 3) proj_gemm(const float* __restrict__ bias) {
    extern __shared__ unsigned smd[];
    const unsigned smb = smem_u32(smd);
    const int m0 = blockIdx.y * BM, n0 = blockIdx.x * BN;
    const int t = threadIdx.x, lane = t & 31, w = t >> 5;
    const int wm = w >> 1, wn = w & 1;
    const int lr = t >> 1, half = t & 1;
    const unsigned* aH = g_xh  + (size_t)(m0 + lr) * 128 + half*4;
    const unsigned* aL = g_xl  + (size_t)(m0 + lr) * 128 + half*4;
    const unsigned* bH = g_wah + (size_t)(n0 + lr) * 128 + half*4;
    const unsigned* bL = g_wal + (size_t)(n0 + lr) * 128 + half*4;
    float acc[2][4][4] = {};
    GEMM_LOOP(ED/BK);

    const int g = lane >> 2, qq = lane & 3;
    #pragma unroll
    for (int mt = 0; mt < 2; mt++) {
        int row = m0 + wm*32 + mt*16 + g;
        #pragma unroll
        for (int nt = 0; nt < 4; nt++) {
            int col = n0 + wn*32 + nt*8 + qq*2;
            float bv0 = bias[col], bv1 = bias[col+1];
            float p0 = acc[mt][nt][0] + bv0, p1 = acc[mt][nt][1] + bv1;
            float p2 = acc[mt][nt][2] + bv0, p3 = acc[mt][nt][3] + bv1;
            unsigned *H, *L; int c;
            if (col < NE)          { H = g_qh; L = g_ql; c = col; }
            else if (col < 2*NE)   { H = g_kh; L = g_kl; c = col - NE; }
            else                   { H = g_vh; L = g_vl; c = col - 2*NE; }
            write_qk(H, L, row,   c, p0, p1);
            write_qk(H, L, row+8, c, p2, p3);
        }
    }
}

// ---------------------------------------------------------------------------
// Kernel 2: scores = (Q·K^T)/16; skip tiles fully above diagonal
// ---------------------------------------------------------------------------
__global__ void __launch_bounds__(256, 3) score_gemm() {
    const int q0 = blockIdx.y * BM, k0 = blockIdx.x * BN;
    if (k0 > q0 + (BM - 1)) return;
    const int bh = blockIdx.z;
    extern __shared__ unsigned smd[];
    const unsigned smb = smem_u32(smd);
    const int t = threadIdx.x, lane = t & 31, w = t >> 5;
    const int wm = w >> 1, wn = w & 1;
    const int lr = t >> 1, half = t & 1;
    const unsigned* aH = g_qh + ((size_t)bh * SQL + q0 + lr) * 128 + half*4;
    const unsigned* aL = g_ql + ((size_t)bh * SQL + q0 + lr) * 128 + half*4;
    const unsigned* bH = g_kh + ((size_t)bh * SQL + k0 + lr) * 128 + half*4;
    const unsigned* bL = g_kl + ((size_t)bh * SQL + k0 + lr) * 128 + half*4;
    float acc[2][4][4] = {};
    GEMM_LOOP(ED/BK);

    float* S = g_scores + (size_t)bh * SQL * SQL;
    const int g = lane >> 2, qq = lane & 3;
    #pragma unroll
    for (int mt = 0; mt < 2; mt++) {
        int row = q0 + wm*32 + mt*16 + g;
        #pragma unroll
        for (int nt = 0; nt < 4; nt++) {
            int col = k0 + wn*32 + nt*8 + qq*2;
            float* d0 = S + (size_t)row * SQL + col;
            float* d1 = S + (size_t)(row+8) * SQL + col;
            *(float2*)d0 = make_float2(acc[mt][nt][0]*0.0625f, acc[mt][nt][1]*0.0625f);
            *(float2*)d1 = make_float2(acc[mt][nt][2]*0.0625f, acc[mt][nt][3]*0.0625f);
        }
    }
}

// ---------------------------------------------------------------------------
// Kernel 3: causal softmax; touches only cols < kend = ceil((q+1)/128)*128
// (cols >= kend are never read by pv). Writes P split-bf16 pairs.
// ---------------------------------------------------------------------------
__global__ void __launch_bounds__(128) softmax_rows() {
    const int row = blockIdx.x;
    const int q = row & (SQL - 1);
    const int kend = ((q >> 7) + 1) << 7;
    const float* r = g_scores + (size_t)row * SQL;
    const int t = threadIdx.x;
    const int k0 = t * 8;
    const bool act = (k0 < kend);
    float v[8];
    float mx = -1e30f;
    if (act) {
        float4 x0 = *(const float4*)(r + k0);
        float4 x1 = *(const float4*)(r + k0 + 4);
        v[0]=x0.x; v[1]=x0.y; v[2]=x0.z; v[3]=x0.w;
        v[4]=x1.x; v[5]=x1.y; v[6]=x1.z; v[7]=x1.w;
        #pragma unroll
        for (int i = 0; i < 8; i++) {
            v[i] = (k0 + i <= q) ? v[i] : -1e30f;
            mx = fmaxf(mx, v[i]);
        }
    }
    __shared__ float redm[4], reds[4];
    #pragma unroll
    for (int o = 16; o > 0; o >>= 1) mx = fmaxf(mx, __shfl_xor_sync(0xffffffffu, mx, o));
    if ((t & 31) == 0) redm[t >> 5] = mx;
    __syncthreads();
    mx = fmaxf(fmaxf(redm[0], redm[1]), fmaxf(redm[2], redm[3]));
    float sum = 0.f;
    if (act) {
        #pragma unroll
        for (int i = 0; i < 8; i++) {
            v[i] = (k0 + i <= q) ? expf(v[i] - mx) : 0.f;
            sum += v[i];
        }
    }
    #pragma unroll
    for (int o = 16; o > 0; o >>= 1) sum += __shfl_xor_sync(0xffffffffu, sum, o);
    if ((t & 31) == 0) reds[t >> 5] = sum;
    __syncthreads();
    sum = reds[0] + reds[1] + reds[2] + reds[3];
    if (act) {
        float inv = 1.f / sum;
        unsigned hh[4], ll[4];
        #pragma unroll
        for (int j = 0; j < 4; j++)
            split2(v[2*j] * inv, v[2*j+1] * inv, hh[j], ll[j]);
        *(uint4*)(g_ph + (size_t)row * 512 + t*4) = make_uint4(hh[0], hh[1], hh[2], hh[3]);
        *(uint4*)(g_pl + (size_t)row * 512 + t*4) = make_uint4(ll[0], ll[1], ll[2], ll[3]);
    }
}

// ---------------------------------------------------------------------------
// Kernel 4: O = P @ V (V natural layout, B frags via ldsm.trans); causal trunc
// ---------------------------------------------------------------------------
__global__ void __launch_bounds__(256, 3) pv_gemm() {
    const int bh = blockIdx.z;
    const int q0 = (int)(gridDim.y - 1 - blockIdx.y) * BM;   // heavy tiles first
    const int n0 = blockIdx.x * BN;
    extern __shared__ unsigned smd[];
    const unsigned smb = smem_u32(smd);
    const int t = threadIdx.x, lane = t & 31, w = t >> 5;
    const int wm = w >> 1, wn = w & 1;
    const int lr = t >> 1, half = t & 1;
    const int NS = (q0 + BM) / BK;
    const unsigned* aH = g_ph + ((size_t)bh * SQL + q0 + lr) * 512 + half*4;
    const unsigned* aL = g_pl + ((size_t)bh * SQL + q0 + lr) * 512 + half*4;
    const unsigned* vbh = g_vh + ((size_t)bh * SQL + (t>>3)) * 128 + (n0>>1) + (t&7)*4;
    const unsigned* vbl = g_vl + ((size_t)bh * SQL + (t>>3)) * 128 + (n0>>1) + (t&7)*4;
    float acc[2][4][4] = {};
    GEMM_LOOP_PV(NS);

    const int g = lane >> 2, qq = lane & 3;
    #pragma unroll
    for (int mt = 0; mt < 2; mt++) {
        int row = q0 + wm*32 + mt*16 + g;
        #pragma unroll
        for (int nt = 0; nt < 4; nt++) {
            int col = n0 + wn*32 + nt*8 + qq*2;
            size_t i0 = ((size_t)bh * SQL + row) * 128 + (col >> 1);
            size_t i1 = ((size_t)bh * SQL + row + 8) * 128 + (col >> 1);
            unsigned hh, ll;
            split2(acc[mt][nt][0], acc[mt][nt][1], hh, ll);
            g_ah[i0] = hh; g_al[i0] = ll;
            split2(acc[mt][nt][2], acc[mt][nt][3], hh, ll);
            g_ah[i1] = hh; g_al[i1] = ll;
        }
    }
}

// ---------------------------------------------------------------------------
// Kernel 5: out partials (split-K=2): g_op[z] = attn_flat @ w_out^T (k-chunk z)
// ---------------------------------------------------------------------------
__global__ void __launch_bounds__(256, 3) out_gemm() {
    extern __shared__ unsigned smd[];
    const unsigned smb = smem_u32(smd);
    const int m0 = blockIdx.y * BM, n0 = blockIdx.x * BN;
    const int z = blockIdx.z;
    float* P = z ? g_op1 : g_op0;
    const int t = threadIdx.x, lane = t & 31, w = t >> 5;
    const int wm = w >> 1, wn = w & 1;
    const int lr = t >> 1, half = t & 1;
    const unsigned* aH = g_ah  + (size_t)(m0 + lr) * 1024 + z*512 + half*4;
    const unsigned* aL = g_al  + (size_t)(m0 + lr) * 1024 + z*512 + half*4;
    const unsigned* bH = g_woh + (size_t)(n0 + lr) * 1024 + z*512 + half*4;
    const unsigned* bL = g_wol + (size_t)(n0 + lr) * 1024 + z*512 + half*4;
    float acc[2][4][4] = {};
    GEMM_LOOP(NE/BK/2);

    const int g = lane >> 2, qq = lane & 3;
    #pragma unroll
    for (int mt = 0; mt < 2; mt++) {
        int row = m0 + wm*32 + mt*16 + g;
        #pragma unroll
        for (int nt = 0; nt < 4; nt++) {
            int col = n0 + wn*32 + nt*8 + qq*2;
            *(float2*)(P + (size_t)row * ED + col) =
                make_float2(acc[mt][nt][0], acc[mt][nt][1]);
            *(float2*)(P + (size_t)(row+8) * ED + col) =
                make_float2(acc[mt][nt][2], acc[mt][nt][3]);
        }
    }
}

// Kernel 6: C = op0 + op1 + bias
__global__ void __launch_bounds__(256) out_reduce(const float* __restrict__ bias,
                                                  float* __restrict__ C) {
    int i = blockIdx.x * 256 + threadIdx.x;       // float4 index
    float4 a = ((const float4*)g_op0)[i];
    float4 b = ((const float4*)g_op1)[i];
    int col = (i * 4) & (ED - 1);
    float4 bb = *(const float4*)(bias + col);
    ((float4*)C)[i] = make_float4(a.x+b.x+bb.x, a.y+b.y+bb.y, a.z+b.z+bb.z, a.w+b.w+bb.w);
}

extern "C" void kernel_launch(void* const* d_in, const int* in_sizes, int n_in,
                              void* d_out, int out_size) {
    const float* x      = (const float*)d_in[0];
    const float* w_attn = (const float*)d_in[1];
    const float* b_attn = (const float*)d_in[2];
    const float* w_out  = (const float*)d_in[3];
    const float* b_out  = (const float*)d_in[4];
    float* out = (float*)d_out;

    cudaFuncSetAttribute(proj_gemm,  cudaFuncAttributeMaxDynamicSharedMemorySize, SMEM_SZ);
    cudaFuncSetAttribute(score_gemm, cudaFuncAttributeMaxDynamicSharedMemorySize, SMEM_SZ);
    cudaFuncSetAttribute(pv_gemm,    cudaFuncAttributeMaxDynamicSharedMemorySize, SMEM_SZ);
    cudaFuncSetAttribute(out_gemm,   cudaFuncAttributeMaxDynamicSharedMemorySize, SMEM_SZ);

    const int NTOT = NXW + NWAW + NWOW;
    split_all<<<(NTOT + 255)/256, 256>>>(x, w_attn, w_out);

    proj_gemm<<<dim3(QKV/BN, TOK/BM), 256, SMEM_SZ>>>(b_attn);
    score_gemm<<<dim3(SQL/BN, SQL/BM, NBH), 256, SMEM_SZ>>>();
    softmax_rows<<<NBH*SQL, 128>>>();
    pv_gemm<<<dim3(ED/BN, SQL/BM, NBH), 256, NPIPE*STG_PV>>>();
    out_gemm<<<dim3(ED/BN, TOK/BM, 2), 256, SMEM_SZ>>>();
    out_reduce<<<TOK*ED/4/256, 256>>>(b_out, out);
}